// round 12
// baseline (speedup 1.0000x reference)
#include <cuda_runtime.h>
#include <cuda_fp16.h>
#include <stdint.h>

#define HD 256
#define NMAX 50048
#define EMAX 800000
#define NGR 64

// ---------------- device scratch (static, no runtime alloc) ----------------
__device__ __half g_aggh[(size_t)NMAX * HD];
__device__ float  g_hbuf[(size_t)NMAX * HD];   // used as fp16 (capacity 2x)
__device__ __half g_x16 [(size_t)NMAX * 128];
__device__ __half g_xah [(size_t)NMAX * HD];
__device__ __half g_xbh [(size_t)NMAX * HD];
__device__ __half g_w1t [128 * 256];           // [n][k] fp16 transposed
__device__ __half g_w2t [256 * 256];
__device__ __half g_w3t [256 * 256];
__device__ int    g_src [EMAX];
__device__ int    g_dstv[EMAX];
__device__ int    g_nbr [EMAX];
__device__ int    g_deg [NMAX];
__device__ int    g_off [NMAX + 1];
__device__ int    g_cur [NMAX];
__device__ int    g_batch[NMAX];
__device__ int    g_bsum[1024];
__device__ float  g_colsum[HD];
__device__ float  g_colsq [HD];
__device__ float  g_pool[NGR * HD];
__device__ float  g_cnt [NGR];

// ---------------- cp.async helpers ----------------
__device__ __forceinline__ void cp16s(uint32_t saddr, const void* g, int sz)
{
    asm volatile("cp.async.cg.shared.global [%0], [%1], 16, %2;" :: "r"(saddr), "l"(g), "r"(sz));
}
#define CP_COMMIT() asm volatile("cp.async.commit_group;")
#define CP_WAIT2()  asm volatile("cp.async.wait_group 2;")
#define CP_WAIT1()  asm volatile("cp.async.wait_group 1;")
#define CP_WAIT0()  asm volatile("cp.async.wait_group 0;")

#define LDSM_X4(r0, r1, r2, r3, addr)                                        \
    asm volatile("ldmatrix.sync.aligned.m8n8.x4.shared.b16 {%0,%1,%2,%3}, [%4];" \
                 : "=r"(r0), "=r"(r1), "=r"(r2), "=r"(r3) : "r"(addr))

#define MMA_F16(d, a, b)                                                          \
    asm volatile("mma.sync.aligned.m16n8k16.row.col.f32.f16.f16.f32 "            \
                 "{%0,%1,%2,%3}, {%4,%5,%6,%7}, {%8,%9}, {%0,%1,%2,%3};"         \
                 : "+f"(d[0]), "+f"(d[1]), "+f"(d[2]), "+f"(d[3])                 \
                 : "r"(a[0]), "r"(a[1]), "r"(a[2]), "r"(a[3]),                    \
                   "r"(b[0]), "r"(b[1]))

// ---------------- fused convert (dtype detect + edges + batch) + x2h + weight transpose ----------------
__global__ void k_convprep(const int* __restrict__ ei, const int* __restrict__ bat,
                           const float* __restrict__ x,
                           const float* __restrict__ W1, const float* __restrict__ W2,
                           const float* __restrict__ W3, int E, int N, int ebl, int nx)
{
    int b = blockIdx.x, t = threadIdx.x;
    if (b < ebl) {
        int e64 = (ei[1] == 0 && ei[3] == 0 && ei[5] == 0 && ei[7] == 0) ? 1 : 0;
        int w = N - 1; if (!(w & 1)) w--;
        int b64 = (bat[w] == 0) ? 1 : 0;
        int i = b * 256 + t;
        if (i < E) {
            int s, d;
            if (e64) { s = ei[2 * i]; d = ei[2 * (E + i)]; }
            else     { s = ei[i];     d = ei[E + i]; }
            g_src[i] = s; g_dstv[i] = d;
            atomicAdd(&g_deg[d], 1);
        }
        if (i < N) g_batch[i] = b64 ? bat[2 * i] : bat[i];
    } else if (b < ebl + nx) {
        int i = (b - ebl) * 256 + t;
        if (i < N * 32) {
            float4 v = ((const float4*)x)[i];
            __half2* o = (__half2*)g_x16;
            o[2 * i]     = __floats2half2_rn(v.x, v.y);
            o[2 * i + 1] = __floats2half2_rn(v.z, v.w);
        }
    } else {
        int wb = b - ebl - nx;             // 0..767
        const float* W = (wb < 256) ? W1 : ((wb < 512) ? W2 : W3);
        __half* Wt = (wb < 256) ? g_w1t : ((wb < 512) ? g_w2t : g_w3t);
        int K = (wb < 256) ? 128 : 256;
        int n = wb & 255;
        for (int k = t; k < K; k += 256)
            Wt[(size_t)n * K + k] = __float2half(W[(size_t)k * HD + n]);
    }
}

// ---------------- per-256-block degree sums ----------------
__global__ void k_bsum(int N)
{
    int t = threadIdx.x;
    int i = blockIdx.x * 256 + t;
    int v = (i < N) ? g_deg[i] : 0;
#pragma unroll
    for (int o = 16; o; o >>= 1) v += __shfl_down_sync(~0u, v, o);
    __shared__ int ws[8];
    if ((t & 31) == 0) ws[t >> 5] = v;
    __syncthreads();
    if (t == 0) {
        int s = 0;
#pragma unroll
        for (int k = 0; k < 8; k++) s += ws[k];
        g_bsum[blockIdx.x] = s;
    }
}

// ---------------- offsets: inline block-prefix reduce + per-block scan; zeroes deg ----------------
__global__ void k_off(int N)
{
    __shared__ int ws[8];
    __shared__ int s_bpre;
    int t = threadIdx.x;
    int lane = t & 31, wid = t >> 5;

    int bv = (t < blockIdx.x) ? g_bsum[t] : 0;
#pragma unroll
    for (int o = 16; o; o >>= 1) bv += __shfl_down_sync(~0u, bv, o);
    if (lane == 0) ws[wid] = bv;
    __syncthreads();
    if (t == 0) {
        int s = 0;
#pragma unroll
        for (int k = 0; k < 8; k++) s += ws[k];
        s_bpre = s;
    }
    __syncthreads();

    int i = blockIdx.x * 256 + t;
    int v = (i < N) ? g_deg[i] : 0;
    int x = v;
#pragma unroll
    for (int o = 1; o < 32; o <<= 1) {
        int y = __shfl_up_sync(~0u, x, o);
        if (lane >= o) x += y;
    }
    __syncthreads();
    if (lane == 31) ws[wid] = x;
    __syncthreads();
    if (t < 8) {
        int y = ws[t];
#pragma unroll
        for (int o = 1; o < 8; o <<= 1) {
            int z = __shfl_up_sync(0xff, y, o);
            if (t >= o) y += z;
        }
        ws[t] = y;
    }
    __syncthreads();
    int incl = x + (wid ? ws[wid - 1] : 0);
    int off = s_bpre + incl - v;
    if (i < N) {
        g_off[i] = off;
        g_cur[i] = off;
        g_deg[i] = 0;          // self-restore for next replay
    }
    if (i == N - 1) g_off[N] = off + v;
}

__global__ void k_fill(int E)
{
    int i = blockIdx.x * blockDim.x + threadIdx.x;
    if (i < E) {
        int d = g_dstv[i];
        int p = atomicAdd(&g_cur[d], 1);
        g_nbr[p] = g_src[i];
    }
}

// ---------------- GIN aggregation (fp16 in/out, fp32 accum) ----------------
__global__ void k_gather128h(__half* __restrict__ out, int N)
{
    if (blockIdx.x == 0) { g_colsum[threadIdx.x] = 0.f; g_colsq[threadIdx.x] = 0.f; }
    int gt = blockIdx.x * blockDim.x + threadIdx.x;
    int w = gt >> 5, lane = gt & 31;
    if (w >= N) return;
    const uint2* xp = (const uint2*)g_x16;
    float acc[4];
    {
        uint2 s = xp[(size_t)w * 32 + lane];
        float2 a = __half22float2(*(const __half2*)&s.x);
        float2 b = __half22float2(*(const __half2*)&s.y);
        acc[0] = a.x; acc[1] = a.y; acc[2] = b.x; acc[3] = b.y;
    }
    int e = g_off[w], e1 = g_off[w + 1];
    for (; e + 1 < e1; e += 2) {
        uint2 s0 = xp[(size_t)g_nbr[e] * 32 + lane];
        uint2 s1 = xp[(size_t)g_nbr[e + 1] * 32 + lane];
        float2 a0 = __half22float2(*(const __half2*)&s0.x);
        float2 b0 = __half22float2(*(const __half2*)&s0.y);
        float2 a1 = __half22float2(*(const __half2*)&s1.x);
        float2 b1 = __half22float2(*(const __half2*)&s1.y);
        acc[0] += a0.x + a1.x; acc[1] += a0.y + a1.y;
        acc[2] += b0.x + b1.x; acc[3] += b0.y + b1.y;
    }
    if (e < e1) {
        uint2 s = xp[(size_t)g_nbr[e] * 32 + lane];
        float2 a = __half22float2(*(const __half2*)&s.x);
        float2 b = __half22float2(*(const __half2*)&s.y);
        acc[0] += a.x; acc[1] += a.y; acc[2] += b.x; acc[3] += b.y;
    }
    __half2 p0 = __floats2half2_rn(acc[0], acc[1]);
    __half2 p1 = __floats2half2_rn(acc[2], acc[3]);
    uint2 pk; pk.x = *(uint32_t*)&p0; pk.y = *(uint32_t*)&p1;
    ((uint2*)out)[(size_t)w * 32 + lane] = pk;
}

__global__ void k_gather256h(const __half* __restrict__ xin, __half* __restrict__ out, int N)
{
    if (blockIdx.x == 0) { g_colsum[threadIdx.x] = 0.f; g_colsq[threadIdx.x] = 0.f; }
    int gt = blockIdx.x * blockDim.x + threadIdx.x;
    int w = gt >> 5, lane = gt & 31;
    if (w >= N) return;
    const uint4* xp = (const uint4*)xin;
    float acc[8];
    {
        uint4 s = xp[(size_t)w * 32 + lane];
        float2 a = __half22float2(*(const __half2*)&s.x);
        float2 b = __half22float2(*(const __half2*)&s.y);
        float2 c = __half22float2(*(const __half2*)&s.z);
        float2 d = __half22float2(*(const __half2*)&s.w);
        acc[0] = a.x; acc[1] = a.y; acc[2] = b.x; acc[3] = b.y;
        acc[4] = c.x; acc[5] = c.y; acc[6] = d.x; acc[7] = d.y;
    }
    int e = g_off[w], e1 = g_off[w + 1];
    for (; e + 1 < e1; e += 2) {
        uint4 s0 = xp[(size_t)g_nbr[e] * 32 + lane];
        uint4 s1 = xp[(size_t)g_nbr[e + 1] * 32 + lane];
        float2 a0 = __half22float2(*(const __half2*)&s0.x);
        float2 b0 = __half22float2(*(const __half2*)&s0.y);
        float2 c0 = __half22float2(*(const __half2*)&s0.z);
        float2 d0 = __half22float2(*(const __half2*)&s0.w);
        float2 a1 = __half22float2(*(const __half2*)&s1.x);
        float2 b1 = __half22float2(*(const __half2*)&s1.y);
        float2 c1 = __half22float2(*(const __half2*)&s1.z);
        float2 d1 = __half22float2(*(const __half2*)&s1.w);
        acc[0] += a0.x + a1.x; acc[1] += a0.y + a1.y;
        acc[2] += b0.x + b1.x; acc[3] += b0.y + b1.y;
        acc[4] += c0.x + c1.x; acc[5] += c0.y + c1.y;
        acc[6] += d0.x + d1.x; acc[7] += d0.y + d1.y;
    }
    if (e < e1) {
        uint4 s = xp[(size_t)g_nbr[e] * 32 + lane];
        float2 a = __half22float2(*(const __half2*)&s.x);
        float2 b = __half22float2(*(const __half2*)&s.y);
        float2 c = __half22float2(*(const __half2*)&s.z);
        float2 d = __half22float2(*(const __half2*)&s.w);
        acc[0] += a.x; acc[1] += a.y; acc[2] += b.x; acc[3] += b.y;
        acc[4] += c.x; acc[5] += c.y; acc[6] += d.x; acc[7] += d.y;
    }
    __half2 p0 = __floats2half2_rn(acc[0], acc[1]);
    __half2 p1 = __floats2half2_rn(acc[2], acc[3]);
    __half2 p2 = __floats2half2_rn(acc[4], acc[5]);
    __half2 p3 = __floats2half2_rn(acc[6], acc[7]);
    uint4 pk;
    pk.x = *(uint32_t*)&p0; pk.y = *(uint32_t*)&p1;
    pk.z = *(uint32_t*)&p2; pk.w = *(uint32_t*)&p3;
    ((uint4*)out)[(size_t)w * 32 + lane] = pk;
}

// ---------------- fp16 mma GEMM: 4-stage cp.async pipeline, prefetch-before-compute ----------------
// H[M,256] = A[M,K](fp16) @ Wt[256,K]^T + bias (fp16 out), fused col sum/sumsq.
template <int K>
__launch_bounds__(256, 2)
__global__ void k_gemm(const __half* __restrict__ A, const __half* __restrict__ Wt,
                       const float* __restrict__ bias, __half* __restrict__ Hout, int M)
{
    const int BK = 32, NIT = K / BK, LDA = 40;
    const int STG = 2 * 128 * LDA * 2;        // 20480 bytes/stage (As + Bs)
    extern __shared__ char dsm[];
    float* RedS = (float*)dsm;
    float* RedQ = (float*)(dsm + 512);
    uint32_t tbase = (uint32_t)__cvta_generic_to_shared(dsm + 1024);

    int bm = blockIdx.x * 128, bn = blockIdx.y * 128;
    int t = threadIdx.x, lane = t & 31, w = t >> 5;
    int m_warp = (w & 1) * 64;
    int n_warp = (w >> 1) * 32;

    if (t < 128) { RedS[t] = 0.f; RedQ[t] = 0.f; }   // ordered by mainloop barriers

    // staging map: rows r0 0..63, r1 64..127; 16B chunk s0
    int r0 = t >> 2, s0 = (t & 3) * 8;
    int r1 = r0 + 64;
    int gA0 = bm + r0, gA1 = bm + r1;
    int az0 = (gA0 < M) ? 16 : 0, az1 = (gA1 < M) ? 16 : 0;
    const __half* apB0 = A + (size_t)gA0 * K + s0;
    const __half* apB1 = A + (size_t)gA1 * K + s0;
    const __half* bpB0 = Wt + (size_t)(bn + r0) * K + s0;
    const __half* bpB1 = Wt + (size_t)(bn + r1) * K + s0;
    uint32_t dA0 = (uint32_t)((r0 * LDA + s0) * 2);
    uint32_t dA1 = (uint32_t)((r1 * LDA + s0) * 2);
    uint32_t dB0 = (uint32_t)(128 * LDA * 2) + dA0;
    uint32_t dB1 = (uint32_t)(128 * LDA * 2) + dA1;

    // ldmatrix per-lane offsets (bytes within a stage)
    uint32_t offA[4], offB[2];
#pragma unroll
    for (int mt = 0; mt < 4; mt++)
        offA[mt] = (uint32_t)(((m_warp + mt * 16 + (lane & 15)) * LDA + (lane >> 4) * 8) * 2);
#pragma unroll
    for (int p = 0; p < 2; p++)
        offB[p] = (uint32_t)(128 * LDA * 2)
                + (uint32_t)(((n_warp + p * 16 + (lane & 7) + (lane >> 4) * 8) * LDA
                             + ((lane >> 3) & 1) * 8) * 2);

    float acc[4][4][4];
#pragma unroll
    for (int mt = 0; mt < 4; mt++)
#pragma unroll
        for (int nt = 0; nt < 4; nt++)
#pragma unroll
            for (int f = 0; f < 4; f++) acc[mt][nt][f] = 0.f;

    // prologue: stage tiles 0, 1, 2
#pragma unroll
    for (int pt = 0; pt < 3; pt++) {
        if (pt < NIT) {
            uint32_t sb = tbase + (uint32_t)pt * STG;
            int k0 = pt * BK;
            cp16s(sb + dA0, apB0 + k0, az0);
            cp16s(sb + dA1, apB1 + k0, az1);
            cp16s(sb + dB0, bpB0 + k0, 16);
            cp16s(sb + dB1, bpB1 + k0, 16);
        }
        CP_COMMIT();   // commit even when empty to keep group accounting uniform
    }

#pragma unroll
    for (int it = 0; it < NIT; it++) {
        // ensure stage it landed (tail-aware wait depth)
        if (it < NIT - 2)      CP_WAIT2();
        else if (it == NIT - 2) CP_WAIT1();
        else                    CP_WAIT0();
        __syncthreads();

        // prefetch stage it+3 FIRST (buffer (it+3)%4 free: last read in iter it-1)
        if (it + 3 < NIT) {
            uint32_t sn = tbase + (uint32_t)((it + 3) % 4) * STG;
            int k0 = (it + 3) * BK;
            cp16s(sn + dA0, apB0 + k0, az0);
            cp16s(sn + dA1, apB1 + k0, az1);
            cp16s(sn + dB0, bpB0 + k0, 16);
            cp16s(sn + dB1, bpB1 + k0, 16);
            CP_COMMIT();
        }

        uint32_t sb = tbase + (uint32_t)(it % 4) * STG;
#pragma unroll
        for (int ks = 0; ks < 2; ks++) {
            uint32_t kb = (uint32_t)(ks * 16 * 2);
            uint32_t af[4][4], bf[4][2];
#pragma unroll
            for (int mt = 0; mt < 4; mt++)
                LDSM_X4(af[mt][0], af[mt][1], af[mt][2], af[mt][3], sb + offA[mt] + kb);
            LDSM_X4(bf[0][0], bf[0][1], bf[1][0], bf[1][1], sb + offB[0] + kb);
            LDSM_X4(bf[2][0], bf[2][1], bf[3][0], bf[3][1], sb + offB[1] + kb);
#pragma unroll
            for (int mt = 0; mt < 4; mt++)
#pragma unroll
                for (int nt = 0; nt < 4; nt++)
                    MMA_F16(acc[mt][nt], af[mt], bf[nt]);
        }
    }
    __syncthreads();   // protect last stage reads + order RedS/Q zeroing before atomics

    // ---- epilogue: bias, fp16 store, per-column sum/sumsq (fp32 exact) ----
    int ar = lane >> 2;
    int ac2 = (lane & 3) * 2;
#pragma unroll
    for (int nt = 0; nt < 4; nt++) {
        int cc = n_warp + nt * 8 + ac2;
        float b0 = bias[bn + cc], b1 = bias[bn + cc + 1];
        float s0a = 0.f, q0 = 0.f, s1a = 0.f, q1 = 0.f;
#pragma unroll
        for (int mt = 0; mt < 4; mt++) {
            int gr0 = bm + m_warp + mt * 16 + ar;
            int gr1 = gr0 + 8;
            if (gr0 < M) {
                float o0 = acc[mt][nt][0] + b0;
                float o1 = acc[mt][nt][1] + b1;
                *(__half2*)(Hout + (size_t)gr0 * HD + bn + cc) = __floats2half2_rn(o0, o1);
                s0a += o0; q0 += o0 * o0; s1a += o1; q1 += o1 * o1;
            }
            if (gr1 < M) {
                float o2 = acc[mt][nt][2] + b0;
                float o3 = acc[mt][nt][3] + b1;
                *(__half2*)(Hout + (size_t)gr1 * HD + bn + cc) = __floats2half2_rn(o2, o3);
                s0a += o2; q0 += o2 * o2; s1a += o3; q1 += o3 * o3;
            }
        }
        atomicAdd(&RedS[cc], s0a);
        atomicAdd(&RedQ[cc], q0);
        atomicAdd(&RedS[cc + 1], s1a);
        atomicAdd(&RedQ[cc + 1], q1);
    }
    __syncthreads();
    if (t < 128) {
        atomicAdd(&g_colsum[bn + t], RedS[t]);
        atomicAdd(&g_colsq[bn + t],  RedQ[t]);
    }
}

// ---------------- BN + ReLU (+ fp16 residual), fp16 in/out; zeroes pool ----------------
__global__ void k_bnrelu_h(const __half* __restrict__ Hin, const float* __restrict__ gam,
                           const float* __restrict__ bet, const __half* __restrict__ resid,
                           __half* __restrict__ out, int M)
{
    if (blockIdx.x < 64) {
        g_pool[blockIdx.x * 256 + threadIdx.x] = 0.f;
        if (blockIdx.x == 0 && threadIdx.x < NGR) g_cnt[threadIdx.x] = 0.f;
    }
    int idx = blockIdx.x * blockDim.x + threadIdx.x;
    if (idx >= M * 32) return;
    int c8 = (idx & 31) * 8;
    float invN = 1.0f / (float)M;
    uint4 hh = ((const uint4*)Hin)[idx];
    float2 h0 = __half22float2(*(const __half2*)&hh.x);
    float2 h1 = __half22float2(*(const __half2*)&hh.y);
    float2 h2 = __half22float2(*(const __half2*)&hh.z);
    float2 h3 = __half22float2(*(const __half2*)&hh.w);
    float hv[8] = { h0.x, h0.y, h1.x, h1.y, h2.x, h2.y, h3.x, h3.y };
    float o[8];
#pragma unroll
    for (int j = 0; j < 8; j++) {
        int c = c8 + j;
        float m = g_colsum[c] * invN;
        float v = fmaf(-m, m, g_colsq[c] * invN);
        float sc = gam[c] * rsqrtf(v + 1e-5f);
        float sh = fmaf(-m, sc, bet[c]);
        o[j] = fmaxf(fmaf(hv[j], sc, sh), 0.0f);
    }
    if (resid) {
        uint4 r = ((const uint4*)resid)[idx];
        float2 r0 = __half22float2(*(const __half2*)&r.x);
        float2 r1 = __half22float2(*(const __half2*)&r.y);
        float2 r2 = __half22float2(*(const __half2*)&r.z);
        float2 r3 = __half22float2(*(const __half2*)&r.w);
        o[0] += r0.x; o[1] += r0.y; o[2] += r1.x; o[3] += r1.y;
        o[4] += r2.x; o[5] += r2.y; o[6] += r3.x; o[7] += r3.y;
    }
    __half2 p0 = __floats2half2_rn(o[0], o[1]);
    __half2 p1 = __floats2half2_rn(o[2], o[3]);
    __half2 p2 = __floats2half2_rn(o[4], o[5]);
    __half2 p3 = __floats2half2_rn(o[6], o[7]);
    uint4 pk;
    pk.x = *(uint32_t*)&p0; pk.y = *(uint32_t*)&p1;
    pk.z = *(uint32_t*)&p2; pk.w = *(uint32_t*)&p3;
    ((uint4*)out)[idx] = pk;
}

// ---------------- pool: batch sorted -> register-accumulate, flush on change ----------------
__global__ void k_pool2(const __half* __restrict__ x3, int N)
{
    __shared__ int sb[128];
    int n0 = blockIdx.x * 128;
    int n1 = n0 + 128; if (n1 > N) n1 = N;
    int t = threadIdx.x;
    if (t < n1 - n0) sb[t] = g_batch[n0 + t];
    __syncthreads();
    if (n1 <= n0) return;
    float acc = 0.f;
    int curg = sb[0], cnt = 0;
    for (int n = n0; n < n1; n++) {
        int g = sb[n - n0];
        if (g != curg) {
            atomicAdd(&g_pool[curg * HD + t], acc);
            if (t == 0) atomicAdd(&g_cnt[curg], (float)cnt);
            acc = 0.f; cnt = 0; curg = g;
        }
        acc += __half2float(x3[(size_t)n * HD + t]);
        cnt++;
    }
    atomicAdd(&g_pool[curg * HD + t], acc);
    if (t == 0) atomicAdd(&g_cnt[curg], (float)cnt);
}

// ---------------- final MLP head (64 graphs) ----------------
__global__ void k_final(const float* __restrict__ fcW1, const float* __restrict__ fcb1,
                        const float* __restrict__ fcW2, const float* __restrict__ fcb2,
                        float* __restrict__ out)
{
    __shared__ float prow[HD];
    __shared__ float hred[HD];
    int g = blockIdx.x, t = threadIdx.x;
    float cnt = fmaxf(g_cnt[g], 1.0f);
    prow[t] = g_pool[g * HD + t] / cnt;
    __syncthreads();
    float acc = fcb1[t];
    for (int k = 0; k < HD; k++)
        acc = fmaf(prow[k], __ldg(fcW1 + (size_t)k * HD + t), acc);
    float h = fmaxf(acc, 0.0f);
    hred[t] = h * fcW2[t];
    __syncthreads();
    for (int s = HD / 2; s > 0; s >>= 1) {
        if (t < s) hred[t] += hred[t + s];
        __syncthreads();
    }
    if (t == 0) out[g] = hred[0] + fcb2[0];
}

// ---------------- launch ----------------
extern "C" void kernel_launch(void* const* d_in, const int* in_sizes, int n_in,
                              void* d_out, int out_size)
{
    int base = 3;
    if (n_in >= 20 && in_sizes[3] == 1) base = 4;

    const float* x   = (const float*)d_in[0];
    const int*   ei  = (const int*)d_in[1];
    const int*   bat = (const int*)d_in[2];
    const float* W1  = (const float*)d_in[base + 0];
    const float* b1  = (const float*)d_in[base + 1];
    const float* W2  = (const float*)d_in[base + 2];
    const float* b2  = (const float*)d_in[base + 3];
    const float* W3  = (const float*)d_in[base + 4];
    const float* b3  = (const float*)d_in[base + 5];
    const float* ga1 = (const float*)d_in[base + 6];
    const float* be1 = (const float*)d_in[base + 7];
    const float* ga2 = (const float*)d_in[base + 8];
    const float* be2 = (const float*)d_in[base + 9];
    const float* ga3 = (const float*)d_in[base + 10];
    const float* be3 = (const float*)d_in[base + 11];
    const float* fcW1 = (const float*)d_in[base + 12];
    const float* fcb1 = (const float*)d_in[base + 13];
    const float* fcW2 = (const float*)d_in[base + 14];
    const float* fcb2 = (const float*)d_in[base + 15];

    int N = in_sizes[0] / 128;
    int E = in_sizes[1] / 2;

    void* p;
    __half *aggh, *xah, *xbh, *w1t, *w2t, *w3t, *hh;
    cudaGetSymbolAddress(&p, g_aggh); aggh = (__half*)p;
    cudaGetSymbolAddress(&p, g_hbuf); hh   = (__half*)p;
    cudaGetSymbolAddress(&p, g_xah);  xah  = (__half*)p;
    cudaGetSymbolAddress(&p, g_xbh);  xbh  = (__half*)p;
    cudaGetSymbolAddress(&p, g_w1t);  w1t  = (__half*)p;
    cudaGetSymbolAddress(&p, g_w2t);  w2t  = (__half*)p;
    cudaGetSymbolAddress(&p, g_w3t);  w3t  = (__half*)p;

    const int SHM = 1024 + 4 * 20480;   // 82944 bytes (4 stages)
    cudaFuncSetAttribute(k_gemm<128>, cudaFuncAttributeMaxDynamicSharedMemorySize, SHM);
    cudaFuncSetAttribute(k_gemm<256>, cudaFuncAttributeMaxDynamicSharedMemorySize, SHM);

    const int tb = 256;
    int ebl = (E + tb - 1) / tb;
    int nb256 = (N + 255) / 256;
    int wbl = (N * 32 + tb - 1) / tb;
    int bnbl = (N * 32 + tb - 1) / tb;
    int nx = (N * 32 + 255) / 256;
    dim3 ggrid((N + 127) / 128, 2);

    // CSR + prep (fused)
    k_convprep<<<ebl + nx + 768, tb>>>(ei, bat, x, W1, W2, W3, E, N, ebl, nx);
    k_bsum<<<nb256, 256>>>(N);
    k_off<<<nb256, 256>>>(N);
    k_fill<<<ebl, tb>>>(E);

    // layer 1: K=128
    k_gather128h<<<wbl, tb>>>(aggh, N);
    k_gemm<128><<<ggrid, 256, SHM>>>(aggh, w1t, b1, hh, N);
    k_bnrelu_h<<<bnbl, tb>>>(hh, ga1, be1, nullptr, xah, N);

    // layer 2
    k_gather256h<<<wbl, tb>>>(xah, aggh, N);
    k_gemm<256><<<ggrid, 256, SHM>>>(aggh, w2t, b2, hh, N);
    k_bnrelu_h<<<bnbl, tb>>>(hh, ga2, be2, xah, xbh, N);

    // layer 3
    k_gather256h<<<wbl, tb>>>(xbh, aggh, N);
    k_gemm<256><<<ggrid, 256, SHM>>>(aggh, w3t, b3, hh, N);
    k_bnrelu_h<<<bnbl, tb>>>(hh, ga3, be3, xbh, xah, N);

    // pool + head
    k_pool2<<<(N + 127) / 128, 256>>>(xah, N);
    k_final<<<NGR, 256>>>(fcW1, fcb1, fcW2, fcb2, (float*)d_out);
}

// round 13
// speedup vs baseline: 1.0291x; 1.0291x over previous
#include <cuda_runtime.h>
#include <cuda_fp16.h>
#include <stdint.h>

#define HD 256
#define NMAX 50048
#define EMAX 800000
#define NGR 64

// ---------------- device scratch (static, no runtime alloc) ----------------
__device__ __half g_aggh[(size_t)NMAX * HD];
__device__ float  g_hbuf[(size_t)NMAX * HD];   // used as fp16 (capacity 2x)
__device__ __half g_x16 [(size_t)NMAX * 128];
__device__ __half g_xah [(size_t)NMAX * HD];
__device__ __half g_xbh [(size_t)NMAX * HD];
__device__ __half g_w1t [128 * 256];           // [n][k] fp16 transposed
__device__ __half g_w2t [256 * 256];
__device__ __half g_w3t [256 * 256];
__device__ int    g_src [EMAX];
__device__ int    g_dstv[EMAX];
__device__ int    g_nbr [EMAX];
__device__ int    g_deg [NMAX];
__device__ int    g_off [NMAX + 1];
__device__ int    g_cur [NMAX];
__device__ int    g_batch[NMAX];
__device__ int    g_bsum[1024];
__device__ float  g_colsum[HD];
__device__ float  g_colsq [HD];
__device__ float  g_pool[NGR * HD];
__device__ float  g_cnt [NGR];

// ---------------- cp.async helpers ----------------
__device__ __forceinline__ void cp16s(uint32_t saddr, const void* g, int sz)
{
    asm volatile("cp.async.cg.shared.global [%0], [%1], 16, %2;" :: "r"(saddr), "l"(g), "r"(sz));
}
#define CP_COMMIT() asm volatile("cp.async.commit_group;")
#define CP_WAIT1()  asm volatile("cp.async.wait_group 1;")
#define CP_WAIT0()  asm volatile("cp.async.wait_group 0;")

#define LDSM_X4(r0, r1, r2, r3, addr)                                        \
    asm volatile("ldmatrix.sync.aligned.m8n8.x4.shared.b16 {%0,%1,%2,%3}, [%4];" \
                 : "=r"(r0), "=r"(r1), "=r"(r2), "=r"(r3) : "r"(addr))

#define MMA_F16(d, a, b)                                                          \
    asm volatile("mma.sync.aligned.m16n8k16.row.col.f32.f16.f16.f32 "            \
                 "{%0,%1,%2,%3}, {%4,%5,%6,%7}, {%8,%9}, {%0,%1,%2,%3};"         \
                 : "+f"(d[0]), "+f"(d[1]), "+f"(d[2]), "+f"(d[3])                 \
                 : "r"(a[0]), "r"(a[1]), "r"(a[2]), "r"(a[3]),                    \
                   "r"(b[0]), "r"(b[1]))

// ---------------- fused convert (dtype detect + edges + batch) + x2h + weight transpose ----------------
__global__ void k_convprep(const int* __restrict__ ei, const int* __restrict__ bat,
                           const float* __restrict__ x,
                           const float* __restrict__ W1, const float* __restrict__ W2,
                           const float* __restrict__ W3, int E, int N, int ebl, int nx)
{
    int b = blockIdx.x, t = threadIdx.x;
    if (b < ebl) {
        int e64 = (ei[1] == 0 && ei[3] == 0 && ei[5] == 0 && ei[7] == 0) ? 1 : 0;
        int w = N - 1; if (!(w & 1)) w--;
        int b64 = (bat[w] == 0) ? 1 : 0;
        int i = b * 256 + t;
        if (i < E) {
            int s, d;
            if (e64) { s = ei[2 * i]; d = ei[2 * (E + i)]; }
            else     { s = ei[i];     d = ei[E + i]; }
            g_src[i] = s; g_dstv[i] = d;
            atomicAdd(&g_deg[d], 1);
        }
        if (i < N) g_batch[i] = b64 ? bat[2 * i] : bat[i];
    } else if (b < ebl + nx) {
        int i = (b - ebl) * 256 + t;
        if (i < N * 32) {
            float4 v = ((const float4*)x)[i];
            __half2* o = (__half2*)g_x16;
            o[2 * i]     = __floats2half2_rn(v.x, v.y);
            o[2 * i + 1] = __floats2half2_rn(v.z, v.w);
        }
    } else {
        int wb = b - ebl - nx;             // 0..767
        const float* W = (wb < 256) ? W1 : ((wb < 512) ? W2 : W3);
        __half* Wt = (wb < 256) ? g_w1t : ((wb < 512) ? g_w2t : g_w3t);
        int K = (wb < 256) ? 128 : 256;
        int n = wb & 255;
        for (int k = t; k < K; k += 256)
            Wt[(size_t)n * K + k] = __float2half(W[(size_t)k * HD + n]);
    }
}

// ---------------- per-256-block degree sums ----------------
__global__ void k_bsum(int N)
{
    int t = threadIdx.x;
    int i = blockIdx.x * 256 + t;
    int v = (i < N) ? g_deg[i] : 0;
#pragma unroll
    for (int o = 16; o; o >>= 1) v += __shfl_down_sync(~0u, v, o);
    __shared__ int ws[8];
    if ((t & 31) == 0) ws[t >> 5] = v;
    __syncthreads();
    if (t == 0) {
        int s = 0;
#pragma unroll
        for (int k = 0; k < 8; k++) s += ws[k];
        g_bsum[blockIdx.x] = s;
    }
}

// ---------------- offsets: inline block-prefix reduce + per-block scan; zeroes deg ----------------
__global__ void k_off(int N)
{
    __shared__ int ws[8];
    __shared__ int s_bpre;
    int t = threadIdx.x;
    int lane = t & 31, wid = t >> 5;

    int bv = (t < blockIdx.x) ? g_bsum[t] : 0;
#pragma unroll
    for (int o = 16; o; o >>= 1) bv += __shfl_down_sync(~0u, bv, o);
    if (lane == 0) ws[wid] = bv;
    __syncthreads();
    if (t == 0) {
        int s = 0;
#pragma unroll
        for (int k = 0; k < 8; k++) s += ws[k];
        s_bpre = s;
    }
    __syncthreads();

    int i = blockIdx.x * 256 + t;
    int v = (i < N) ? g_deg[i] : 0;
    int x = v;
#pragma unroll
    for (int o = 1; o < 32; o <<= 1) {
        int y = __shfl_up_sync(~0u, x, o);
        if (lane >= o) x += y;
    }
    __syncthreads();
    if (lane == 31) ws[wid] = x;
    __syncthreads();
    if (t < 8) {
        int y = ws[t];
#pragma unroll
        for (int o = 1; o < 8; o <<= 1) {
            int z = __shfl_up_sync(0xff, y, o);
            if (t >= o) y += z;
        }
        ws[t] = y;
    }
    __syncthreads();
    int incl = x + (wid ? ws[wid - 1] : 0);
    int off = s_bpre + incl - v;
    if (i < N) {
        g_off[i] = off;
        g_cur[i] = off;
        g_deg[i] = 0;          // self-restore for next replay
    }
    if (i == N - 1) g_off[N] = off + v;
}

__global__ void k_fill(int E)
{
    int i = blockIdx.x * blockDim.x + threadIdx.x;
    if (i < E) {
        int d = g_dstv[i];
        int p = atomicAdd(&g_cur[d], 1);
        g_nbr[p] = g_src[i];
    }
}

// ---------------- GIN aggregation (fp16 in/out, fp32 accum), unroll-4 for MLP ----------------
__global__ void k_gather128h(__half* __restrict__ out, int N)
{
    if (blockIdx.x == 0) { g_colsum[threadIdx.x] = 0.f; g_colsq[threadIdx.x] = 0.f; }
    int gt = blockIdx.x * blockDim.x + threadIdx.x;
    int w = gt >> 5, lane = gt & 31;
    if (w >= N) return;
    const uint2* xp = (const uint2*)g_x16;
    float acc[4];
    {
        uint2 s = xp[(size_t)w * 32 + lane];
        float2 a = __half22float2(*(const __half2*)&s.x);
        float2 b = __half22float2(*(const __half2*)&s.y);
        acc[0] = a.x; acc[1] = a.y; acc[2] = b.x; acc[3] = b.y;
    }
    int e = g_off[w], e1 = g_off[w + 1];
    for (; e + 3 < e1; e += 4) {
        int n0 = g_nbr[e], n1 = g_nbr[e + 1], n2 = g_nbr[e + 2], n3 = g_nbr[e + 3];
        uint2 s0 = xp[(size_t)n0 * 32 + lane];
        uint2 s1 = xp[(size_t)n1 * 32 + lane];
        uint2 s2 = xp[(size_t)n2 * 32 + lane];
        uint2 s3 = xp[(size_t)n3 * 32 + lane];
        float2 a0 = __half22float2(*(const __half2*)&s0.x), b0 = __half22float2(*(const __half2*)&s0.y);
        float2 a1 = __half22float2(*(const __half2*)&s1.x), b1 = __half22float2(*(const __half2*)&s1.y);
        float2 a2 = __half22float2(*(const __half2*)&s2.x), b2 = __half22float2(*(const __half2*)&s2.y);
        float2 a3 = __half22float2(*(const __half2*)&s3.x), b3 = __half22float2(*(const __half2*)&s3.y);
        acc[0] += (a0.x + a1.x) + (a2.x + a3.x);
        acc[1] += (a0.y + a1.y) + (a2.y + a3.y);
        acc[2] += (b0.x + b1.x) + (b2.x + b3.x);
        acc[3] += (b0.y + b1.y) + (b2.y + b3.y);
    }
    for (; e < e1; e++) {
        uint2 s = xp[(size_t)g_nbr[e] * 32 + lane];
        float2 a = __half22float2(*(const __half2*)&s.x);
        float2 b = __half22float2(*(const __half2*)&s.y);
        acc[0] += a.x; acc[1] += a.y; acc[2] += b.x; acc[3] += b.y;
    }
    __half2 p0 = __floats2half2_rn(acc[0], acc[1]);
    __half2 p1 = __floats2half2_rn(acc[2], acc[3]);
    uint2 pk; pk.x = *(uint32_t*)&p0; pk.y = *(uint32_t*)&p1;
    ((uint2*)out)[(size_t)w * 32 + lane] = pk;
}

__global__ void k_gather256h(const __half* __restrict__ xin, __half* __restrict__ out, int N)
{
    if (blockIdx.x == 0) { g_colsum[threadIdx.x] = 0.f; g_colsq[threadIdx.x] = 0.f; }
    int gt = blockIdx.x * blockDim.x + threadIdx.x;
    int w = gt >> 5, lane = gt & 31;
    if (w >= N) return;
    const uint4* xp = (const uint4*)xin;
    float acc[8];
    {
        uint4 s = xp[(size_t)w * 32 + lane];
        float2 a = __half22float2(*(const __half2*)&s.x);
        float2 b = __half22float2(*(const __half2*)&s.y);
        float2 c = __half22float2(*(const __half2*)&s.z);
        float2 d = __half22float2(*(const __half2*)&s.w);
        acc[0] = a.x; acc[1] = a.y; acc[2] = b.x; acc[3] = b.y;
        acc[4] = c.x; acc[5] = c.y; acc[6] = d.x; acc[7] = d.y;
    }
    int e = g_off[w], e1 = g_off[w + 1];
    for (; e + 3 < e1; e += 4) {
        int n0 = g_nbr[e], n1 = g_nbr[e + 1], n2 = g_nbr[e + 2], n3 = g_nbr[e + 3];
        uint4 s0 = xp[(size_t)n0 * 32 + lane];
        uint4 s1 = xp[(size_t)n1 * 32 + lane];
        uint4 s2 = xp[(size_t)n2 * 32 + lane];
        uint4 s3 = xp[(size_t)n3 * 32 + lane];
#pragma unroll
        for (int q = 0; q < 1; q++) {   // scope for temps
            float2 v;
            v = __half22float2(*(const __half2*)&s0.x); acc[0] += v.x; acc[1] += v.y;
            v = __half22float2(*(const __half2*)&s0.y); acc[2] += v.x; acc[3] += v.y;
            v = __half22float2(*(const __half2*)&s0.z); acc[4] += v.x; acc[5] += v.y;
            v = __half22float2(*(const __half2*)&s0.w); acc[6] += v.x; acc[7] += v.y;
            v = __half22float2(*(const __half2*)&s1.x); acc[0] += v.x; acc[1] += v.y;
            v = __half22float2(*(const __half2*)&s1.y); acc[2] += v.x; acc[3] += v.y;
            v = __half22float2(*(const __half2*)&s1.z); acc[4] += v.x; acc[5] += v.y;
            v = __half22float2(*(const __half2*)&s1.w); acc[6] += v.x; acc[7] += v.y;
            v = __half22float2(*(const __half2*)&s2.x); acc[0] += v.x; acc[1] += v.y;
            v = __half22float2(*(const __half2*)&s2.y); acc[2] += v.x; acc[3] += v.y;
            v = __half22float2(*(const __half2*)&s2.z); acc[4] += v.x; acc[5] += v.y;
            v = __half22float2(*(const __half2*)&s2.w); acc[6] += v.x; acc[7] += v.y;
            v = __half22float2(*(const __half2*)&s3.x); acc[0] += v.x; acc[1] += v.y;
            v = __half22float2(*(const __half2*)&s3.y); acc[2] += v.x; acc[3] += v.y;
            v = __half22float2(*(const __half2*)&s3.z); acc[4] += v.x; acc[5] += v.y;
            v = __half22float2(*(const __half2*)&s3.w); acc[6] += v.x; acc[7] += v.y;
        }
    }
    for (; e < e1; e++) {
        uint4 s = xp[(size_t)g_nbr[e] * 32 + lane];
        float2 a = __half22float2(*(const __half2*)&s.x);
        float2 b = __half22float2(*(const __half2*)&s.y);
        float2 c = __half22float2(*(const __half2*)&s.z);
        float2 d = __half22float2(*(const __half2*)&s.w);
        acc[0] += a.x; acc[1] += a.y; acc[2] += b.x; acc[3] += b.y;
        acc[4] += c.x; acc[5] += c.y; acc[6] += d.x; acc[7] += d.y;
    }
    __half2 p0 = __floats2half2_rn(acc[0], acc[1]);
    __half2 p1 = __floats2half2_rn(acc[2], acc[3]);
    __half2 p2 = __floats2half2_rn(acc[4], acc[5]);
    __half2 p3 = __floats2half2_rn(acc[6], acc[7]);
    uint4 pk;
    pk.x = *(uint32_t*)&p0; pk.y = *(uint32_t*)&p1;
    pk.z = *(uint32_t*)&p2; pk.w = *(uint32_t*)&p3;
    ((uint4*)out)[(size_t)w * 32 + lane] = pk;
}

// ---------------- fp16 mma GEMM: 3-stage cp.async pipeline, 1 barrier/iter (R11 proven) ----------------
template <int K>
__launch_bounds__(256, 2)
__global__ void k_gemm(const __half* __restrict__ A, const __half* __restrict__ Wt,
                       const float* __restrict__ bias, __half* __restrict__ Hout, int M)
{
    const int BK = 32, NIT = K / BK, LDA = 40;
    const int STG = 2 * 128 * LDA * 2;        // 20480 bytes/stage (As + Bs)
    extern __shared__ char dsm[];
    float* RedS = (float*)dsm;
    float* RedQ = (float*)(dsm + 512);
    uint32_t tbase = (uint32_t)__cvta_generic_to_shared(dsm + 1024);

    int bm = blockIdx.x * 128, bn = blockIdx.y * 128;
    int t = threadIdx.x, lane = t & 31, w = t >> 5;
    int m_warp = (w & 1) * 64;
    int n_warp = (w >> 1) * 32;

    if (t < 128) { RedS[t] = 0.f; RedQ[t] = 0.f; }   // ordered by mainloop barriers

    int r0 = t >> 2, s0 = (t & 3) * 8;
    int r1 = r0 + 64;
    int gA0 = bm + r0, gA1 = bm + r1;
    int az0 = (gA0 < M) ? 16 : 0, az1 = (gA1 < M) ? 16 : 0;
    const __half* apB0 = A + (size_t)gA0 * K + s0;
    const __half* apB1 = A + (size_t)gA1 * K + s0;
    const __half* bpB0 = Wt + (size_t)(bn + r0) * K + s0;
    const __half* bpB1 = Wt + (size_t)(bn + r1) * K + s0;
    uint32_t dA0 = (uint32_t)((r0 * LDA + s0) * 2);
    uint32_t dA1 = (uint32_t)((r1 * LDA + s0) * 2);
    uint32_t dB0 = (uint32_t)(128 * LDA * 2) + dA0;
    uint32_t dB1 = (uint32_t)(128 * LDA * 2) + dA1;

    uint32_t offA[4], offB[2];
#pragma unroll
    for (int mt = 0; mt < 4; mt++)
        offA[mt] = (uint32_t)(((m_warp + mt * 16 + (lane & 15)) * LDA + (lane >> 4) * 8) * 2);
#pragma unroll
    for (int p = 0; p < 2; p++)
        offB[p] = (uint32_t)(128 * LDA * 2)
                + (uint32_t)(((n_warp + p * 16 + (lane & 7) + (lane >> 4) * 8) * LDA
                             + ((lane >> 3) & 1) * 8) * 2);

    float acc[4][4][4];
#pragma unroll
    for (int mt = 0; mt < 4; mt++)
#pragma unroll
        for (int nt = 0; nt < 4; nt++)
#pragma unroll
            for (int f = 0; f < 4; f++) acc[mt][nt][f] = 0.f;

    // prologue: stage tiles 0 and 1
#pragma unroll
    for (int pt = 0; pt < 2; pt++) {
        uint32_t sb = tbase + (uint32_t)pt * STG;
        int k0 = pt * BK;
        cp16s(sb + dA0, apB0 + k0, az0);
        cp16s(sb + dA1, apB1 + k0, az1);
        cp16s(sb + dB0, bpB0 + k0, 16);
        cp16s(sb + dB1, bpB1 + k0, 16);
        CP_COMMIT();
    }

#pragma unroll
    for (int it = 0; it < NIT; it++) {
        if (it < NIT - 1) CP_WAIT1(); else CP_WAIT0();
        __syncthreads();
        uint32_t sb = tbase + (uint32_t)(it % 3) * STG;
#pragma unroll
        for (int ks = 0; ks < 2; ks++) {
            uint32_t kb = (uint32_t)(ks * 16 * 2);
            uint32_t af[4][4], bf[4][2];
#pragma unroll
            for (int mt = 0; mt < 4; mt++)
                LDSM_X4(af[mt][0], af[mt][1], af[mt][2], af[mt][3], sb + offA[mt] + kb);
            LDSM_X4(bf[0][0], bf[0][1], bf[1][0], bf[1][1], sb + offB[0] + kb);
            LDSM_X4(bf[2][0], bf[2][1], bf[3][0], bf[3][1], sb + offB[1] + kb);
#pragma unroll
            for (int mt = 0; mt < 4; mt++)
#pragma unroll
                for (int nt = 0; nt < 4; nt++)
                    MMA_F16(acc[mt][nt], af[mt], bf[nt]);
        }
        if (it + 2 < NIT) {
            uint32_t sn = tbase + (uint32_t)((it + 2) % 3) * STG;
            int k0 = (it + 2) * BK;
            cp16s(sn + dA0, apB0 + k0, az0);
            cp16s(sn + dA1, apB1 + k0, az1);
            cp16s(sn + dB0, bpB0 + k0, 16);
            cp16s(sn + dB1, bpB1 + k0, 16);
            CP_COMMIT();
        }
    }
    __syncthreads();

    // ---- epilogue: bias, fp16 store, per-column sum/sumsq (fp32 exact) ----
    int ar = lane >> 2;
    int ac2 = (lane & 3) * 2;
#pragma unroll
    for (int nt = 0; nt < 4; nt++) {
        int cc = n_warp + nt * 8 + ac2;
        float b0 = bias[bn + cc], b1 = bias[bn + cc + 1];
        float s0a = 0.f, q0 = 0.f, s1a = 0.f, q1 = 0.f;
#pragma unroll
        for (int mt = 0; mt < 4; mt++) {
            int gr0 = bm + m_warp + mt * 16 + ar;
            int gr1 = gr0 + 8;
            if (gr0 < M) {
                float o0 = acc[mt][nt][0] + b0;
                float o1 = acc[mt][nt][1] + b1;
                *(__half2*)(Hout + (size_t)gr0 * HD + bn + cc) = __floats2half2_rn(o0, o1);
                s0a += o0; q0 += o0 * o0; s1a += o1; q1 += o1 * o1;
            }
            if (gr1 < M) {
                float o2 = acc[mt][nt][2] + b0;
                float o3 = acc[mt][nt][3] + b1;
                *(__half2*)(Hout + (size_t)gr1 * HD + bn + cc) = __floats2half2_rn(o2, o3);
                s0a += o2; q0 += o2 * o2; s1a += o3; q1 += o3 * o3;
            }
        }
        atomicAdd(&RedS[cc], s0a);
        atomicAdd(&RedQ[cc], q0);
        atomicAdd(&RedS[cc + 1], s1a);
        atomicAdd(&RedQ[cc + 1], q1);
    }
    __syncthreads();
    if (t < 128) {
        atomicAdd(&g_colsum[bn + t], RedS[t]);
        atomicAdd(&g_colsq[bn + t],  RedQ[t]);
    }
}

// ---------------- BN + ReLU (+ fp16 residual), fp16 in/out; zeroes pool ----------------
__global__ void k_bnrelu_h(const __half* __restrict__ Hin, const float* __restrict__ gam,
                           const float* __restrict__ bet, const __half* __restrict__ resid,
                           __half* __restrict__ out, int M)
{
    if (blockIdx.x < 64) {
        g_pool[blockIdx.x * 256 + threadIdx.x] = 0.f;
        if (blockIdx.x == 0 && threadIdx.x < NGR) g_cnt[threadIdx.x] = 0.f;
    }
    int idx = blockIdx.x * blockDim.x + threadIdx.x;
    if (idx >= M * 32) return;
    int c8 = (idx & 31) * 8;
    float invN = 1.0f / (float)M;
    uint4 hh = ((const uint4*)Hin)[idx];
    float2 h0 = __half22float2(*(const __half2*)&hh.x);
    float2 h1 = __half22float2(*(const __half2*)&hh.y);
    float2 h2 = __half22float2(*(const __half2*)&hh.z);
    float2 h3 = __half22float2(*(const __half2*)&hh.w);
    float hv[8] = { h0.x, h0.y, h1.x, h1.y, h2.x, h2.y, h3.x, h3.y };
    float o[8];
#pragma unroll
    for (int j = 0; j < 8; j++) {
        int c = c8 + j;
        float m = g_colsum[c] * invN;
        float v = fmaf(-m, m, g_colsq[c] * invN);
        float sc = gam[c] * rsqrtf(v + 1e-5f);
        float sh = fmaf(-m, sc, bet[c]);
        o[j] = fmaxf(fmaf(hv[j], sc, sh), 0.0f);
    }
    if (resid) {
        uint4 r = ((const uint4*)resid)[idx];
        float2 r0 = __half22float2(*(const __half2*)&r.x);
        float2 r1 = __half22float2(*(const __half2*)&r.y);
        float2 r2 = __half22float2(*(const __half2*)&r.z);
        float2 r3 = __half22float2(*(const __half2*)&r.w);
        o[0] += r0.x; o[1] += r0.y; o[2] += r1.x; o[3] += r1.y;
        o[4] += r2.x; o[5] += r2.y; o[6] += r3.x; o[7] += r3.y;
    }
    __half2 p0 = __floats2half2_rn(o[0], o[1]);
    __half2 p1 = __floats2half2_rn(o[2], o[3]);
    __half2 p2 = __floats2half2_rn(o[4], o[5]);
    __half2 p3 = __floats2half2_rn(o[6], o[7]);
    uint4 pk;
    pk.x = *(uint32_t*)&p0; pk.y = *(uint32_t*)&p1;
    pk.z = *(uint32_t*)&p2; pk.w = *(uint32_t*)&p3;
    ((uint4*)out)[idx] = pk;
}

// ---------------- pool: batch sorted -> register-accumulate, flush on change ----------------
__global__ void k_pool2(const __half* __restrict__ x3, int N)
{
    __shared__ int sb[128];
    int n0 = blockIdx.x * 128;
    int n1 = n0 + 128; if (n1 > N) n1 = N;
    int t = threadIdx.x;
    if (t < n1 - n0) sb[t] = g_batch[n0 + t];
    __syncthreads();
    if (n1 <= n0) return;
    float acc = 0.f;
    int curg = sb[0], cnt = 0;
    for (int n = n0; n < n1; n++) {
        int g = sb[n - n0];
        if (g != curg) {
            atomicAdd(&g_pool[curg * HD + t], acc);
            if (t == 0) atomicAdd(&g_cnt[curg], (float)cnt);
            acc = 0.f; cnt = 0; curg = g;
        }
        acc += __half2float(x3[(size_t)n * HD + t]);
        cnt++;
    }
    atomicAdd(&g_pool[curg * HD + t], acc);
    if (t == 0) atomicAdd(&g_cnt[curg], (float)cnt);
}

// ---------------- final MLP head (64 graphs) ----------------
__global__ void k_final(const float* __restrict__ fcW1, const float* __restrict__ fcb1,
                        const float* __restrict__ fcW2, const float* __restrict__ fcb2,
                        float* __restrict__ out)
{
    __shared__ float prow[HD];
    __shared__ float hred[HD];
    int g = blockIdx.x, t = threadIdx.x;
    float cnt = fmaxf(g_cnt[g], 1.0f);
    prow[t] = g_pool[g * HD + t] / cnt;
    __syncthreads();
    float acc = fcb1[t];
    for (int k = 0; k < HD; k++)
        acc = fmaf(prow[k], __ldg(fcW1 + (size_t)k * HD + t), acc);
    float h = fmaxf(acc, 0.0f);
    hred[t] = h * fcW2[t];
    __syncthreads();
    for (int s = HD / 2; s > 0; s >>= 1) {
        if (t < s) hred[t] += hred[t + s];
        __syncthreads();
    }
    if (t == 0) out[g] = hred[0] + fcb2[0];
}

// ---------------- launch ----------------
extern "C" void kernel_launch(void* const* d_in, const int* in_sizes, int n_in,
                              void* d_out, int out_size)
{
    int base = 3;
    if (n_in >= 20 && in_sizes[3] == 1) base = 4;

    const float* x   = (const float*)d_in[0];
    const int*   ei  = (const int*)d_in[1];
    const int*   bat = (const int*)d_in[2];
    const float* W1  = (const float*)d_in[base + 0];
    const float* b1  = (const float*)d_in[base + 1];
    const float* W2  = (const float*)d_in[base + 2];
    const float* b2  = (const float*)d_in[base + 3];
    const float* W3  = (const float*)d_in[base + 4];
    const float* b3  = (const float*)d_in[base + 5];
    const float* ga1 = (const float*)d_in[base + 6];
    const float* be1 = (const float*)d_in[base + 7];
    const float* ga2 = (const float*)d_in[base + 8];
    const float* be2 = (const float*)d_in[base + 9];
    const float* ga3 = (const float*)d_in[base + 10];
    const float* be3 = (const float*)d_in[base + 11];
    const float* fcW1 = (const float*)d_in[base + 12];
    const float* fcb1 = (const float*)d_in[base + 13];
    const float* fcW2 = (const float*)d_in[base + 14];
    const float* fcb2 = (const float*)d_in[base + 15];

    int N = in_sizes[0] / 128;
    int E = in_sizes[1] / 2;

    void* p;
    __half *aggh, *xah, *xbh, *w1t, *w2t, *w3t, *hh;
    cudaGetSymbolAddress(&p, g_aggh); aggh = (__half*)p;
    cudaGetSymbolAddress(&p, g_hbuf); hh   = (__half*)p;
    cudaGetSymbolAddress(&p, g_xah);  xah  = (__half*)p;
    cudaGetSymbolAddress(&p, g_xbh);  xbh  = (__half*)p;
    cudaGetSymbolAddress(&p, g_w1t);  w1t  = (__half*)p;
    cudaGetSymbolAddress(&p, g_w2t);  w2t  = (__half*)p;
    cudaGetSymbolAddress(&p, g_w3t);  w3t  = (__half*)p;

    const int SHM = 1024 + 3 * 20480;   // 62464 bytes (3 stages)
    cudaFuncSetAttribute(k_gemm<128>, cudaFuncAttributeMaxDynamicSharedMemorySize, SHM);
    cudaFuncSetAttribute(k_gemm<256>, cudaFuncAttributeMaxDynamicSharedMemorySize, SHM);

    const int tb = 256;
    int ebl = (E + tb - 1) / tb;
    int nb256 = (N + 255) / 256;
    int wbl = (N * 32 + tb - 1) / tb;
    int bnbl = (N * 32 + tb - 1) / tb;
    int nx = (N * 32 + 255) / 256;
    dim3 ggrid((N + 127) / 128, 2);

    // CSR + prep (fused)
    k_convprep<<<ebl + nx + 768, tb>>>(ei, bat, x, W1, W2, W3, E, N, ebl, nx);
    k_bsum<<<nb256, 256>>>(N);
    k_off<<<nb256, 256>>>(N);
    k_fill<<<ebl, tb>>>(E);

    // layer 1: K=128
    k_gather128h<<<wbl, tb>>>(aggh, N);
    k_gemm<128><<<ggrid, 256, SHM>>>(aggh, w1t, b1, hh, N);
    k_bnrelu_h<<<bnbl, tb>>>(hh, ga1, be1, nullptr, xah, N);

    // layer 2
    k_gather256h<<<wbl, tb>>>(xah, aggh, N);
    k_gemm<256><<<ggrid, 256, SHM>>>(aggh, w2t, b2, hh, N);
    k_bnrelu_h<<<bnbl, tb>>>(hh, ga2, be2, xah, xbh, N);

    // layer 3
    k_gather256h<<<wbl, tb>>>(xbh, aggh, N);
    k_gemm<256><<<ggrid, 256, SHM>>>(aggh, w3t, b3, hh, N);
    k_bnrelu_h<<<bnbl, tb>>>(hh, ga3, be3, xbh, xah, N);

    // pool + head
    k_pool2<<<(N + 127) / 128, 256>>>(xah, N);
    k_final<<<NGR, 256>>>(fcW1, fcb1, fcW2, fcb2, (float*)d_out);
}

// round 14
// speedup vs baseline: 1.0331x; 1.0039x over previous
#include <cuda_runtime.h>
#include <cuda_fp16.h>
#include <stdint.h>

#define HD 256
#define NMAX 50048
#define EMAX 800000
#define NGR 64

// ---------------- device scratch (static, no runtime alloc) ----------------
__device__ __half g_aggh[(size_t)NMAX * HD];
__device__ float  g_hbuf[(size_t)NMAX * HD];   // used as fp16 (capacity 2x)
__device__ __half g_x16 [(size_t)NMAX * 128];
__device__ __half g_xah [(size_t)NMAX * HD];
__device__ __half g_xbh [(size_t)NMAX * HD];
__device__ __half g_w1t [128 * 256];           // [n][k] fp16 transposed
__device__ __half g_w2t [256 * 256];
__device__ __half g_w3t [256 * 256];
__device__ int    g_src [EMAX];
__device__ int    g_dstv[EMAX];
__device__ int    g_nbr [EMAX];
__device__ int    g_deg [NMAX];
__device__ int    g_off [NMAX + 1];
__device__ int    g_cur [NMAX];
__device__ int    g_batch[NMAX];
__device__ int    g_bsum[1024];
__device__ float  g_colsum[HD];
__device__ float  g_colsq [HD];
__device__ float  g_pool[NGR * HD];
__device__ float  g_cnt [NGR];

// ---------------- cp.async helpers ----------------
__device__ __forceinline__ void cp16s(uint32_t saddr, const void* g, int sz)
{
    asm volatile("cp.async.cg.shared.global [%0], [%1], 16, %2;" :: "r"(saddr), "l"(g), "r"(sz));
}
#define CP_COMMIT() asm volatile("cp.async.commit_group;")
#define CP_WAIT1()  asm volatile("cp.async.wait_group 1;")
#define CP_WAIT0()  asm volatile("cp.async.wait_group 0;")

#define LDSM_X4(r0, r1, r2, r3, addr)                                        \
    asm volatile("ldmatrix.sync.aligned.m8n8.x4.shared.b16 {%0,%1,%2,%3}, [%4];" \
                 : "=r"(r0), "=r"(r1), "=r"(r2), "=r"(r3) : "r"(addr))

#define MMA_F16(d, a, b)                                                          \
    asm volatile("mma.sync.aligned.m16n8k16.row.col.f32.f16.f16.f32 "            \
                 "{%0,%1,%2,%3}, {%4,%5,%6,%7}, {%8,%9}, {%0,%1,%2,%3};"         \
                 : "+f"(d[0]), "+f"(d[1]), "+f"(d[2]), "+f"(d[3])                 \
                 : "r"(a[0]), "r"(a[1]), "r"(a[2]), "r"(a[3]),                    \
                   "r"(b[0]), "r"(b[1]))

// ---------------- fused convert (dtype detect + edges + batch) + x2h + weight transpose ----------------
__global__ void k_convprep(const int* __restrict__ ei, const int* __restrict__ bat,
                           const float* __restrict__ x,
                           const float* __restrict__ W1, const float* __restrict__ W2,
                           const float* __restrict__ W3, int E, int N, int ebl, int nx)
{
    int b = blockIdx.x, t = threadIdx.x;
    if (b < ebl) {
        int e64 = (ei[1] == 0 && ei[3] == 0 && ei[5] == 0 && ei[7] == 0) ? 1 : 0;
        int w = N - 1; if (!(w & 1)) w--;
        int b64 = (bat[w] == 0) ? 1 : 0;
        int i = b * 256 + t;
        if (i < E) {
            int s, d;
            if (e64) { s = ei[2 * i]; d = ei[2 * (E + i)]; }
            else     { s = ei[i];     d = ei[E + i]; }
            g_src[i] = s; g_dstv[i] = d;
            atomicAdd(&g_deg[d], 1);
        }
        if (i < N) g_batch[i] = b64 ? bat[2 * i] : bat[i];
    } else if (b < ebl + nx) {
        int i = (b - ebl) * 256 + t;
        if (i < N * 32) {
            float4 v = ((const float4*)x)[i];
            __half2* o = (__half2*)g_x16;
            o[2 * i]     = __floats2half2_rn(v.x, v.y);
            o[2 * i + 1] = __floats2half2_rn(v.z, v.w);
        }
    } else {
        int wb = b - ebl - nx;             // 0..767
        const float* W = (wb < 256) ? W1 : ((wb < 512) ? W2 : W3);
        __half* Wt = (wb < 256) ? g_w1t : ((wb < 512) ? g_w2t : g_w3t);
        int K = (wb < 256) ? 128 : 256;
        int n = wb & 255;
        for (int k = t; k < K; k += 256)
            Wt[(size_t)n * K + k] = __float2half(W[(size_t)k * HD + n]);
    }
}

// ---------------- per-256-block degree sums ----------------
__global__ void k_bsum(int N)
{
    int t = threadIdx.x;
    int i = blockIdx.x * 256 + t;
    int v = (i < N) ? g_deg[i] : 0;
#pragma unroll
    for (int o = 16; o; o >>= 1) v += __shfl_down_sync(~0u, v, o);
    __shared__ int ws[8];
    if ((t & 31) == 0) ws[t >> 5] = v;
    __syncthreads();
    if (t == 0) {
        int s = 0;
#pragma unroll
        for (int k = 0; k < 8; k++) s += ws[k];
        g_bsum[blockIdx.x] = s;
    }
}

// ---------------- offsets: inline block-prefix reduce + per-block scan; zeroes deg ----------------
__global__ void k_off(int N)
{
    __shared__ int ws[8];
    __shared__ int s_bpre;
    int t = threadIdx.x;
    int lane = t & 31, wid = t >> 5;

    int bv = (t < blockIdx.x) ? g_bsum[t] : 0;
#pragma unroll
    for (int o = 16; o; o >>= 1) bv += __shfl_down_sync(~0u, bv, o);
    if (lane == 0) ws[wid] = bv;
    __syncthreads();
    if (t == 0) {
        int s = 0;
#pragma unroll
        for (int k = 0; k < 8; k++) s += ws[k];
        s_bpre = s;
    }
    __syncthreads();

    int i = blockIdx.x * 256 + t;
    int v = (i < N) ? g_deg[i] : 0;
    int x = v;
#pragma unroll
    for (int o = 1; o < 32; o <<= 1) {
        int y = __shfl_up_sync(~0u, x, o);
        if (lane >= o) x += y;
    }
    __syncthreads();
    if (lane == 31) ws[wid] = x;
    __syncthreads();
    if (t < 8) {
        int y = ws[t];
#pragma unroll
        for (int o = 1; o < 8; o <<= 1) {
            int z = __shfl_up_sync(0xff, y, o);
            if (t >= o) y += z;
        }
        ws[t] = y;
    }
    __syncthreads();
    int incl = x + (wid ? ws[wid - 1] : 0);
    int off = s_bpre + incl - v;
    if (i < N) {
        g_off[i] = off;
        g_cur[i] = off;
        g_deg[i] = 0;          // self-restore for next replay
    }
    if (i == N - 1) g_off[N] = off + v;
}

__global__ void k_fill(int E)
{
    int i = blockIdx.x * blockDim.x + threadIdx.x;
    if (i < E) {
        int d = g_dstv[i];
        int p = atomicAdd(&g_cur[d], 1);
        g_nbr[p] = g_src[i];
    }
}

// ---------------- GIN aggregation (fp16 in/out, fp32 accum), unroll-8 ----------------
__global__ void k_gather128h(__half* __restrict__ out, int N)
{
    if (blockIdx.x == 0) { g_colsum[threadIdx.x] = 0.f; g_colsq[threadIdx.x] = 0.f; }
    int gt = blockIdx.x * blockDim.x + threadIdx.x;
    int w = gt >> 5, lane = gt & 31;
    if (w >= N) return;
    const uint2* xp = (const uint2*)g_x16;
    float acc[4];
    {
        uint2 s = xp[(size_t)w * 32 + lane];
        float2 a = __half22float2(*(const __half2*)&s.x);
        float2 b = __half22float2(*(const __half2*)&s.y);
        acc[0] = a.x; acc[1] = a.y; acc[2] = b.x; acc[3] = b.y;
    }
    int e = g_off[w], e1 = g_off[w + 1];
    for (; e + 7 < e1; e += 8) {
        uint2 s[8];
#pragma unroll
        for (int u = 0; u < 8; u++) s[u] = xp[(size_t)g_nbr[e + u] * 32 + lane];
#pragma unroll
        for (int u = 0; u < 8; u++) {
            float2 a = __half22float2(*(const __half2*)&s[u].x);
            float2 b = __half22float2(*(const __half2*)&s[u].y);
            acc[0] += a.x; acc[1] += a.y; acc[2] += b.x; acc[3] += b.y;
        }
    }
    for (; e + 1 < e1; e += 2) {
        uint2 s0 = xp[(size_t)g_nbr[e] * 32 + lane];
        uint2 s1 = xp[(size_t)g_nbr[e + 1] * 32 + lane];
        float2 a0 = __half22float2(*(const __half2*)&s0.x), b0 = __half22float2(*(const __half2*)&s0.y);
        float2 a1 = __half22float2(*(const __half2*)&s1.x), b1 = __half22float2(*(const __half2*)&s1.y);
        acc[0] += a0.x + a1.x; acc[1] += a0.y + a1.y;
        acc[2] += b0.x + b1.x; acc[3] += b0.y + b1.y;
    }
    if (e < e1) {
        uint2 s = xp[(size_t)g_nbr[e] * 32 + lane];
        float2 a = __half22float2(*(const __half2*)&s.x);
        float2 b = __half22float2(*(const __half2*)&s.y);
        acc[0] += a.x; acc[1] += a.y; acc[2] += b.x; acc[3] += b.y;
    }
    __half2 p0 = __floats2half2_rn(acc[0], acc[1]);
    __half2 p1 = __floats2half2_rn(acc[2], acc[3]);
    uint2 pk; pk.x = *(uint32_t*)&p0; pk.y = *(uint32_t*)&p1;
    ((uint2*)out)[(size_t)w * 32 + lane] = pk;
}

__global__ void k_gather256h(const __half* __restrict__ xin, __half* __restrict__ out, int N)
{
    if (blockIdx.x == 0) { g_colsum[threadIdx.x] = 0.f; g_colsq[threadIdx.x] = 0.f; }
    int gt = blockIdx.x * blockDim.x + threadIdx.x;
    int w = gt >> 5, lane = gt & 31;
    if (w >= N) return;
    const uint4* xp = (const uint4*)xin;
    float acc[8];
    {
        uint4 s = xp[(size_t)w * 32 + lane];
        float2 a = __half22float2(*(const __half2*)&s.x);
        float2 b = __half22float2(*(const __half2*)&s.y);
        float2 c = __half22float2(*(const __half2*)&s.z);
        float2 d = __half22float2(*(const __half2*)&s.w);
        acc[0] = a.x; acc[1] = a.y; acc[2] = b.x; acc[3] = b.y;
        acc[4] = c.x; acc[5] = c.y; acc[6] = d.x; acc[7] = d.y;
    }
    int e = g_off[w], e1 = g_off[w + 1];
    for (; e + 7 < e1; e += 8) {
        uint4 s[8];
#pragma unroll
        for (int u = 0; u < 8; u++) s[u] = xp[(size_t)g_nbr[e + u] * 32 + lane];
#pragma unroll
        for (int u = 0; u < 8; u++) {
            float2 v;
            v = __half22float2(*(const __half2*)&s[u].x); acc[0] += v.x; acc[1] += v.y;
            v = __half22float2(*(const __half2*)&s[u].y); acc[2] += v.x; acc[3] += v.y;
            v = __half22float2(*(const __half2*)&s[u].z); acc[4] += v.x; acc[5] += v.y;
            v = __half22float2(*(const __half2*)&s[u].w); acc[6] += v.x; acc[7] += v.y;
        }
    }
    for (; e + 3 < e1; e += 4) {
        uint4 s[4];
#pragma unroll
        for (int u = 0; u < 4; u++) s[u] = xp[(size_t)g_nbr[e + u] * 32 + lane];
#pragma unroll
        for (int u = 0; u < 4; u++) {
            float2 v;
            v = __half22float2(*(const __half2*)&s[u].x); acc[0] += v.x; acc[1] += v.y;
            v = __half22float2(*(const __half2*)&s[u].y); acc[2] += v.x; acc[3] += v.y;
            v = __half22float2(*(const __half2*)&s[u].z); acc[4] += v.x; acc[5] += v.y;
            v = __half22float2(*(const __half2*)&s[u].w); acc[6] += v.x; acc[7] += v.y;
        }
    }
    for (; e < e1; e++) {
        uint4 s = xp[(size_t)g_nbr[e] * 32 + lane];
        float2 a = __half22float2(*(const __half2*)&s.x);
        float2 b = __half22float2(*(const __half2*)&s.y);
        float2 c = __half22float2(*(const __half2*)&s.z);
        float2 d = __half22float2(*(const __half2*)&s.w);
        acc[0] += a.x; acc[1] += a.y; acc[2] += b.x; acc[3] += b.y;
        acc[4] += c.x; acc[5] += c.y; acc[6] += d.x; acc[7] += d.y;
    }
    __half2 p0 = __floats2half2_rn(acc[0], acc[1]);
    __half2 p1 = __floats2half2_rn(acc[2], acc[3]);
    __half2 p2 = __floats2half2_rn(acc[4], acc[5]);
    __half2 p3 = __floats2half2_rn(acc[6], acc[7]);
    uint4 pk;
    pk.x = *(uint32_t*)&p0; pk.y = *(uint32_t*)&p1;
    pk.z = *(uint32_t*)&p2; pk.w = *(uint32_t*)&p3;
    ((uint4*)out)[(size_t)w * 32 + lane] = pk;
}

// ---------------- fp16 mma GEMM: 3-stage cp.async pipeline, 1 barrier/iter (R11 proven) ----------------
template <int K>
__launch_bounds__(256, 2)
__global__ void k_gemm(const __half* __restrict__ A, const __half* __restrict__ Wt,
                       const float* __restrict__ bias, __half* __restrict__ Hout, int M)
{
    const int BK = 32, NIT = K / BK, LDA = 40;
    const int STG = 2 * 128 * LDA * 2;        // 20480 bytes/stage (As + Bs)
    extern __shared__ char dsm[];
    float* RedS = (float*)dsm;
    float* RedQ = (float*)(dsm + 512);
    uint32_t tbase = (uint32_t)__cvta_generic_to_shared(dsm + 1024);

    int bm = blockIdx.x * 128, bn = blockIdx.y * 128;
    int t = threadIdx.x, lane = t & 31, w = t >> 5;
    int m_warp = (w & 1) * 64;
    int n_warp = (w >> 1) * 32;

    if (t < 128) { RedS[t] = 0.f; RedQ[t] = 0.f; }   // ordered by mainloop barriers

    int r0 = t >> 2, s0 = (t & 3) * 8;
    int r1 = r0 + 64;
    int gA0 = bm + r0, gA1 = bm + r1;
    int az0 = (gA0 < M) ? 16 : 0, az1 = (gA1 < M) ? 16 : 0;
    const __half* apB0 = A + (size_t)gA0 * K + s0;
    const __half* apB1 = A + (size_t)gA1 * K + s0;
    const __half* bpB0 = Wt + (size_t)(bn + r0) * K + s0;
    const __half* bpB1 = Wt + (size_t)(bn + r1) * K + s0;
    uint32_t dA0 = (uint32_t)((r0 * LDA + s0) * 2);
    uint32_t dA1 = (uint32_t)((r1 * LDA + s0) * 2);
    uint32_t dB0 = (uint32_t)(128 * LDA * 2) + dA0;
    uint32_t dB1 = (uint32_t)(128 * LDA * 2) + dA1;

    uint32_t offA[4], offB[2];
#pragma unroll
    for (int mt = 0; mt < 4; mt++)
        offA[mt] = (uint32_t)(((m_warp + mt * 16 + (lane & 15)) * LDA + (lane >> 4) * 8) * 2);
#pragma unroll
    for (int p = 0; p < 2; p++)
        offB[p] = (uint32_t)(128 * LDA * 2)
                + (uint32_t)(((n_warp + p * 16 + (lane & 7) + (lane >> 4) * 8) * LDA
                             + ((lane >> 3) & 1) * 8) * 2);

    float acc[4][4][4];
#pragma unroll
    for (int mt = 0; mt < 4; mt++)
#pragma unroll
        for (int nt = 0; nt < 4; nt++)
#pragma unroll
            for (int f = 0; f < 4; f++) acc[mt][nt][f] = 0.f;

    // prologue: stage tiles 0 and 1
#pragma unroll
    for (int pt = 0; pt < 2; pt++) {
        uint32_t sb = tbase + (uint32_t)pt * STG;
        int k0 = pt * BK;
        cp16s(sb + dA0, apB0 + k0, az0);
        cp16s(sb + dA1, apB1 + k0, az1);
        cp16s(sb + dB0, bpB0 + k0, 16);
        cp16s(sb + dB1, bpB1 + k0, 16);
        CP_COMMIT();
    }

#pragma unroll
    for (int it = 0; it < NIT; it++) {
        if (it < NIT - 1) CP_WAIT1(); else CP_WAIT0();
        __syncthreads();
        uint32_t sb = tbase + (uint32_t)(it % 3) * STG;
#pragma unroll
        for (int ks = 0; ks < 2; ks++) {
            uint32_t kb = (uint32_t)(ks * 16 * 2);
            uint32_t af[4][4], bf[4][2];
#pragma unroll
            for (int mt = 0; mt < 4; mt++)
                LDSM_X4(af[mt][0], af[mt][1], af[mt][2], af[mt][3], sb + offA[mt] + kb);
            LDSM_X4(bf[0][0], bf[0][1], bf[1][0], bf[1][1], sb + offB[0] + kb);
            LDSM_X4(bf[2][0], bf[2][1], bf[3][0], bf[3][1], sb + offB[1] + kb);
#pragma unroll
            for (int mt = 0; mt < 4; mt++)
#pragma unroll
                for (int nt = 0; nt < 4; nt++)
                    MMA_F16(acc[mt][nt], af[mt], bf[nt]);
        }
        if (it + 2 < NIT) {
            uint32_t sn = tbase + (uint32_t)((it + 2) % 3) * STG;
            int k0 = (it + 2) * BK;
            cp16s(sn + dA0, apB0 + k0, az0);
            cp16s(sn + dA1, apB1 + k0, az1);
            cp16s(sn + dB0, bpB0 + k0, 16);
            cp16s(sn + dB1, bpB1 + k0, 16);
            CP_COMMIT();
        }
    }
    __syncthreads();

    // ---- epilogue: bias, fp16 store, per-column sum/sumsq (fp32 exact) ----
    int ar = lane >> 2;
    int ac2 = (lane & 3) * 2;
#pragma unroll
    for (int nt = 0; nt < 4; nt++) {
        int cc = n_warp + nt * 8 + ac2;
        float b0 = bias[bn + cc], b1 = bias[bn + cc + 1];
        float s0a = 0.f, q0 = 0.f, s1a = 0.f, q1 = 0.f;
#pragma unroll
        for (int mt = 0; mt < 4; mt++) {
            int gr0 = bm + m_warp + mt * 16 + ar;
            int gr1 = gr0 + 8;
            if (gr0 < M) {
                float o0 = acc[mt][nt][0] + b0;
                float o1 = acc[mt][nt][1] + b1;
                *(__half2*)(Hout + (size_t)gr0 * HD + bn + cc) = __floats2half2_rn(o0, o1);
                s0a += o0; q0 += o0 * o0; s1a += o1; q1 += o1 * o1;
            }
            if (gr1 < M) {
                float o2 = acc[mt][nt][2] + b0;
                float o3 = acc[mt][nt][3] + b1;
                *(__half2*)(Hout + (size_t)gr1 * HD + bn + cc) = __floats2half2_rn(o2, o3);
                s0a += o2; q0 += o2 * o2; s1a += o3; q1 += o3 * o3;
            }
        }
        atomicAdd(&RedS[cc], s0a);
        atomicAdd(&RedQ[cc], q0);
        atomicAdd(&RedS[cc + 1], s1a);
        atomicAdd(&RedQ[cc + 1], q1);
    }
    __syncthreads();
    if (t < 128) {
        atomicAdd(&g_colsum[bn + t], RedS[t]);
        atomicAdd(&g_colsq[bn + t],  RedQ[t]);
    }
}

// ---------------- BN + ReLU (+ fp16 residual), fp16 in/out; zeroes pool ----------------
__global__ void k_bnrelu_h(const __half* __restrict__ Hin, const float* __restrict__ gam,
                           const float* __restrict__ bet, const __half* __restrict__ resid,
                           __half* __restrict__ out, int M)
{
    if (blockIdx.x < 64) {
        g_pool[blockIdx.x * 256 + threadIdx.x] = 0.f;
        if (blockIdx.x == 0 && threadIdx.x < NGR) g_cnt[threadIdx.x] = 0.f;
    }
    int idx = blockIdx.x * blockDim.x + threadIdx.x;
    if (idx >= M * 32) return;
    int c8 = (idx & 31) * 8;
    float invN = 1.0f / (float)M;
    uint4 hh = ((const uint4*)Hin)[idx];
    float2 h0 = __half22float2(*(const __half2*)&hh.x);
    float2 h1 = __half22float2(*(const __half2*)&hh.y);
    float2 h2 = __half22float2(*(const __half2*)&hh.z);
    float2 h3 = __half22float2(*(const __half2*)&hh.w);
    float hv[8] = { h0.x, h0.y, h1.x, h1.y, h2.x, h2.y, h3.x, h3.y };
    float o[8];
#pragma unroll
    for (int j = 0; j < 8; j++) {
        int c = c8 + j;
        float m = g_colsum[c] * invN;
        float v = fmaf(-m, m, g_colsq[c] * invN);
        float sc = gam[c] * rsqrtf(v + 1e-5f);
        float sh = fmaf(-m, sc, bet[c]);
        o[j] = fmaxf(fmaf(hv[j], sc, sh), 0.0f);
    }
    if (resid) {
        uint4 r = ((const uint4*)resid)[idx];
        float2 r0 = __half22float2(*(const __half2*)&r.x);
        float2 r1 = __half22float2(*(const __half2*)&r.y);
        float2 r2 = __half22float2(*(const __half2*)&r.z);
        float2 r3 = __half22float2(*(const __half2*)&r.w);
        o[0] += r0.x; o[1] += r0.y; o[2] += r1.x; o[3] += r1.y;
        o[4] += r2.x; o[5] += r2.y; o[6] += r3.x; o[7] += r3.y;
    }
    __half2 p0 = __floats2half2_rn(o[0], o[1]);
    __half2 p1 = __floats2half2_rn(o[2], o[3]);
    __half2 p2 = __floats2half2_rn(o[4], o[5]);
    __half2 p3 = __floats2half2_rn(o[6], o[7]);
    uint4 pk;
    pk.x = *(uint32_t*)&p0; pk.y = *(uint32_t*)&p1;
    pk.z = *(uint32_t*)&p2; pk.w = *(uint32_t*)&p3;
    ((uint4*)out)[idx] = pk;
}

// ---------------- pool: batch sorted -> register-accumulate, flush on change ----------------
__global__ void k_pool2(const __half* __restrict__ x3, int N)
{
    __shared__ int sb[128];
    int n0 = blockIdx.x * 128;
    int n1 = n0 + 128; if (n1 > N) n1 = N;
    int t = threadIdx.x;
    if (t < n1 - n0) sb[t] = g_batch[n0 + t];
    __syncthreads();
    if (n1 <= n0) return;
    float acc = 0.f;
    int curg = sb[0], cnt = 0;
    for (int n = n0; n < n1; n++) {
        int g = sb[n - n0];
        if (g != curg) {
            atomicAdd(&g_pool[curg * HD + t], acc);
            if (t == 0) atomicAdd(&g_cnt[curg], (float)cnt);
            acc = 0.f; cnt = 0; curg = g;
        }
        acc += __half2float(x3[(size_t)n * HD + t]);
        cnt++;
    }
    atomicAdd(&g_pool[curg * HD + t], acc);
    if (t == 0) atomicAdd(&g_cnt[curg], (float)cnt);
}

// ---------------- final MLP head (64 graphs) ----------------
__global__ void k_final(const float* __restrict__ fcW1, const float* __restrict__ fcb1,
                        const float* __restrict__ fcW2, const float* __restrict__ fcb2,
                        float* __restrict__ out)
{
    __shared__ float prow[HD];
    __shared__ float hred[HD];
    int g = blockIdx.x, t = threadIdx.x;
    float cnt = fmaxf(g_cnt[g], 1.0f);
    prow[t] = g_pool[g * HD + t] / cnt;
    __syncthreads();
    float acc = fcb1[t];
    for (int k = 0; k < HD; k++)
        acc = fmaf(prow[k], __ldg(fcW1 + (size_t)k * HD + t), acc);
    float h = fmaxf(acc, 0.0f);
    hred[t] = h * fcW2[t];
    __syncthreads();
    for (int s = HD / 2; s > 0; s >>= 1) {
        if (t < s) hred[t] += hred[t + s];
        __syncthreads();
    }
    if (t == 0) out[g] = hred[0] + fcb2[0];
}

// ---------------- launch ----------------
extern "C" void kernel_launch(void* const* d_in, const int* in_sizes, int n_in,
                              void* d_out, int out_size)
{
    int base = 3;
    if (n_in >= 20 && in_sizes[3] == 1) base = 4;

    const float* x   = (const float*)d_in[0];
    const int*   ei  = (const int*)d_in[1];
    const int*   bat = (const int*)d_in[2];
    const float* W1  = (const float*)d_in[base + 0];
    const float* b1  = (const float*)d_in[base + 1];
    const float* W2  = (const float*)d_in[base + 2];
    const float* b2  = (const float*)d_in[base + 3];
    const float* W3  = (const float*)d_in[base + 4];
    const float* b3  = (const float*)d_in[base + 5];
    const float* ga1 = (const float*)d_in[base + 6];
    const float* be1 = (const float*)d_in[base + 7];
    const float* ga2 = (const float*)d_in[base + 8];
    const float* be2 = (const float*)d_in[base + 9];
    const float* ga3 = (const float*)d_in[base + 10];
    const float* be3 = (const float*)d_in[base + 11];
    const float* fcW1 = (const float*)d_in[base + 12];
    const float* fcb1 = (const float*)d_in[base + 13];
    const float* fcW2 = (const float*)d_in[base + 14];
    const float* fcb2 = (const float*)d_in[base + 15];

    int N = in_sizes[0] / 128;
    int E = in_sizes[1] / 2;

    void* p;
    __half *aggh, *xah, *xbh, *w1t, *w2t, *w3t, *hh;
    cudaGetSymbolAddress(&p, g_aggh); aggh = (__half*)p;
    cudaGetSymbolAddress(&p, g_hbuf); hh   = (__half*)p;
    cudaGetSymbolAddress(&p, g_xah);  xah  = (__half*)p;
    cudaGetSymbolAddress(&p, g_xbh);  xbh  = (__half*)p;
    cudaGetSymbolAddress(&p, g_w1t);  w1t  = (__half*)p;
    cudaGetSymbolAddress(&p, g_w2t);  w2t  = (__half*)p;
    cudaGetSymbolAddress(&p, g_w3t);  w3t  = (__half*)p;

    const int SHM = 1024 + 3 * 20480;   // 62464 bytes (3 stages)
    cudaFuncSetAttribute(k_gemm<128>, cudaFuncAttributeMaxDynamicSharedMemorySize, SHM);
    cudaFuncSetAttribute(k_gemm<256>, cudaFuncAttributeMaxDynamicSharedMemorySize, SHM);

    const int tb = 256;
    int ebl = (E + tb - 1) / tb;
    int nb256 = (N + 255) / 256;
    int wbl = (N * 32 + tb - 1) / tb;
    int bnbl = (N * 32 + tb - 1) / tb;
    int nx = (N * 32 + 255) / 256;
    dim3 ggrid((N + 127) / 128, 2);

    // CSR + prep (fused)
    k_convprep<<<ebl + nx + 768, tb>>>(ei, bat, x, W1, W2, W3, E, N, ebl, nx);
    k_bsum<<<nb256, 256>>>(N);
    k_off<<<nb256, 256>>>(N);
    k_fill<<<ebl, tb>>>(E);

    // layer 1: K=128
    k_gather128h<<<wbl, tb>>>(aggh, N);
    k_gemm<128><<<ggrid, 256, SHM>>>(aggh, w1t, b1, hh, N);
    k_bnrelu_h<<<bnbl, tb>>>(hh, ga1, be1, nullptr, xah, N);

    // layer 2
    k_gather256h<<<wbl, tb>>>(xah, aggh, N);
    k_gemm<256><<<ggrid, 256, SHM>>>(aggh, w2t, b2, hh, N);
    k_bnrelu_h<<<bnbl, tb>>>(hh, ga2, be2, xah, xbh, N);

    // layer 3
    k_gather256h<<<wbl, tb>>>(xbh, aggh, N);
    k_gemm<256><<<ggrid, 256, SHM>>>(aggh, w3t, b3, hh, N);
    k_bnrelu_h<<<bnbl, tb>>>(hh, ga3, be3, xbh, xah, N);

    // pool + head
    k_pool2<<<(N + 127) / 128, 256>>>(xah, N);
    k_final<<<NGR, 256>>>(fcW1, fcb1, fcW2, fcb2, (float*)d_out);
}

// round 15
// speedup vs baseline: 1.3029x; 1.2611x over previous
#include <cuda_runtime.h>
#include <cuda_fp16.h>
#include <stdint.h>

#define HD 256
#define NMAX 50048
#define EMAX 800000
#define NGR 64

// ---------------- device scratch (static, no runtime alloc) ----------------
__device__ __half g_aggh[(size_t)NMAX * HD];
__device__ float  g_hbuf[(size_t)NMAX * HD];   // holds TWO fp16 buffers: h_a, h_b
__device__ __half g_x16 [(size_t)NMAX * 128];
__device__ __half g_xah [(size_t)NMAX * HD];   // x3 / scratch
__device__ __half g_xbh [(size_t)NMAX * HD];   // xb (layer-2 output)
__device__ __half g_w1t [128 * 256];           // [n][k] fp16 transposed
__device__ __half g_w2t [256 * 256];
__device__ __half g_w3t [256 * 256];
__device__ int    g_src [EMAX];
__device__ int    g_dstv[EMAX];
__device__ int    g_nbr [EMAX];
__device__ int    g_deg [NMAX];
__device__ int    g_off [NMAX + 1];
__device__ int    g_cur [NMAX];
__device__ int    g_batch[NMAX];
__device__ int    g_bsum[1024];
__device__ float  g_cs[2 * HD];                // stats ping-pong: buf0 / buf1
__device__ float  g_cq[2 * HD];
__device__ float  g_pool[NGR * HD];
__device__ float  g_cnt [NGR];

// ---------------- cp.async helpers ----------------
__device__ __forceinline__ void cp16s(uint32_t saddr, const void* g, int sz)
{
    asm volatile("cp.async.cg.shared.global [%0], [%1], 16, %2;" :: "r"(saddr), "l"(g), "r"(sz));
}
#define CP_COMMIT() asm volatile("cp.async.commit_group;")
#define CP_WAIT1()  asm volatile("cp.async.wait_group 1;")
#define CP_WAIT0()  asm volatile("cp.async.wait_group 0;")

#define LDSM_X4(r0, r1, r2, r3, addr)                                        \
    asm volatile("ldmatrix.sync.aligned.m8n8.x4.shared.b16 {%0,%1,%2,%3}, [%4];" \
                 : "=r"(r0), "=r"(r1), "=r"(r2), "=r"(r3) : "r"(addr))

#define MMA_F16(d, a, b)                                                          \
    asm volatile("mma.sync.aligned.m16n8k16.row.col.f32.f16.f16.f32 "            \
                 "{%0,%1,%2,%3}, {%4,%5,%6,%7}, {%8,%9}, {%0,%1,%2,%3};"         \
                 : "+f"(d[0]), "+f"(d[1]), "+f"(d[2]), "+f"(d[3])                 \
                 : "r"(a[0]), "r"(a[1]), "r"(a[2]), "r"(a[3]),                    \
                   "r"(b[0]), "r"(b[1]))

// ---------------- fused convert + x2h + weight transpose ----------------
__global__ void k_convprep(const int* __restrict__ ei, const int* __restrict__ bat,
                           const float* __restrict__ x,
                           const float* __restrict__ W1, const float* __restrict__ W2,
                           const float* __restrict__ W3, int E, int N, int ebl, int nx)
{
    int b = blockIdx.x, t = threadIdx.x;
    if (b < ebl) {
        int e64 = (ei[1] == 0 && ei[3] == 0 && ei[5] == 0 && ei[7] == 0) ? 1 : 0;
        int w = N - 1; if (!(w & 1)) w--;
        int b64 = (bat[w] == 0) ? 1 : 0;
        int i = b * 256 + t;
        if (i < E) {
            int s, d;
            if (e64) { s = ei[2 * i]; d = ei[2 * (E + i)]; }
            else     { s = ei[i];     d = ei[E + i]; }
            g_src[i] = s; g_dstv[i] = d;
            atomicAdd(&g_deg[d], 1);
        }
        if (i < N) g_batch[i] = b64 ? bat[2 * i] : bat[i];
    } else if (b < ebl + nx) {
        int i = (b - ebl) * 256 + t;
        if (i < N * 32) {
            float4 v = ((const float4*)x)[i];
            __half2* o = (__half2*)g_x16;
            o[2 * i]     = __floats2half2_rn(v.x, v.y);
            o[2 * i + 1] = __floats2half2_rn(v.z, v.w);
        }
    } else {
        int wb = b - ebl - nx;
        const float* W = (wb < 256) ? W1 : ((wb < 512) ? W2 : W3);
        __half* Wt = (wb < 256) ? g_w1t : ((wb < 512) ? g_w2t : g_w3t);
        int K = (wb < 256) ? 128 : 256;
        int n = wb & 255;
        for (int k = t; k < K; k += 256)
            Wt[(size_t)n * K + k] = __float2half(W[(size_t)k * HD + n]);
    }
}

// ---------------- CSR scan pipeline ----------------
__global__ void k_bsum(int N)
{
    int t = threadIdx.x;
    int i = blockIdx.x * 256 + t;
    int v = (i < N) ? g_deg[i] : 0;
#pragma unroll
    for (int o = 16; o; o >>= 1) v += __shfl_down_sync(~0u, v, o);
    __shared__ int ws[8];
    if ((t & 31) == 0) ws[t >> 5] = v;
    __syncthreads();
    if (t == 0) {
        int s = 0;
#pragma unroll
        for (int k = 0; k < 8; k++) s += ws[k];
        g_bsum[blockIdx.x] = s;
    }
}

__global__ void k_off(int N)
{
    __shared__ int ws[8];
    __shared__ int s_bpre;
    int t = threadIdx.x;
    int lane = t & 31, wid = t >> 5;

    int bv = (t < blockIdx.x) ? g_bsum[t] : 0;
#pragma unroll
    for (int o = 16; o; o >>= 1) bv += __shfl_down_sync(~0u, bv, o);
    if (lane == 0) ws[wid] = bv;
    __syncthreads();
    if (t == 0) {
        int s = 0;
#pragma unroll
        for (int k = 0; k < 8; k++) s += ws[k];
        s_bpre = s;
    }
    __syncthreads();

    int i = blockIdx.x * 256 + t;
    int v = (i < N) ? g_deg[i] : 0;
    int x = v;
#pragma unroll
    for (int o = 1; o < 32; o <<= 1) {
        int y = __shfl_up_sync(~0u, x, o);
        if (lane >= o) x += y;
    }
    __syncthreads();
    if (lane == 31) ws[wid] = x;
    __syncthreads();
    if (t < 8) {
        int y = ws[t];
#pragma unroll
        for (int o = 1; o < 8; o <<= 1) {
            int z = __shfl_up_sync(0xff, y, o);
            if (t >= o) y += z;
        }
        ws[t] = y;
    }
    __syncthreads();
    int incl = x + (wid ? ws[wid - 1] : 0);
    int off = s_bpre + incl - v;
    if (i < N) {
        g_off[i] = off;
        g_cur[i] = off;
        g_deg[i] = 0;
    }
    if (i == N - 1) g_off[N] = off + v;
}

__global__ void k_fill(int E)
{
    int i = blockIdx.x * blockDim.x + threadIdx.x;
    if (i < E) {
        int d = g_dstv[i];
        int p = atomicAdd(&g_cur[d], 1);
        g_nbr[p] = g_src[i];
    }
}

// ---------------- layer-1 gather (fp16 x, zeros stats buf0), unroll-8 ----------------
__global__ void k_gather128h(__half* __restrict__ out, int N)
{
    if (blockIdx.x == 0 && threadIdx.x < HD) { g_cs[threadIdx.x] = 0.f; g_cq[threadIdx.x] = 0.f; }
    int gt = blockIdx.x * blockDim.x + threadIdx.x;
    int w = gt >> 5, lane = gt & 31;
    if (w >= N) return;
    const uint2* xp = (const uint2*)g_x16;
    float acc[4];
    {
        uint2 s = xp[(size_t)w * 32 + lane];
        float2 a = __half22float2(*(const __half2*)&s.x);
        float2 b = __half22float2(*(const __half2*)&s.y);
        acc[0] = a.x; acc[1] = a.y; acc[2] = b.x; acc[3] = b.y;
    }
    int e = g_off[w], e1 = g_off[w + 1];
    for (; e + 7 < e1; e += 8) {
        uint2 s[8];
#pragma unroll
        for (int u = 0; u < 8; u++) s[u] = xp[(size_t)g_nbr[e + u] * 32 + lane];
#pragma unroll
        for (int u = 0; u < 8; u++) {
            float2 a = __half22float2(*(const __half2*)&s[u].x);
            float2 b = __half22float2(*(const __half2*)&s[u].y);
            acc[0] += a.x; acc[1] += a.y; acc[2] += b.x; acc[3] += b.y;
        }
    }
    for (; e < e1; e++) {
        uint2 s = xp[(size_t)g_nbr[e] * 32 + lane];
        float2 a = __half22float2(*(const __half2*)&s.x);
        float2 b = __half22float2(*(const __half2*)&s.y);
        acc[0] += a.x; acc[1] += a.y; acc[2] += b.x; acc[3] += b.y;
    }
    __half2 p0 = __floats2half2_rn(acc[0], acc[1]);
    __half2 p1 = __floats2half2_rn(acc[2], acc[3]);
    uint2 pk; pk.x = *(uint32_t*)&p0; pk.y = *(uint32_t*)&p1;
    ((uint2*)out)[(size_t)w * 32 + lane] = pk;
}

// ---------------- layer-2 gather with fused BN1+ReLU on raw h1; zeros stats buf1 ----------------
__global__ void k_gather256bn(const __half* __restrict__ h1, __half* __restrict__ out,
                              const float* __restrict__ gam, const float* __restrict__ bet,
                              int N)
{
    __shared__ float ssc[HD], ssh[HD];
    int t = threadIdx.x;
    if (blockIdx.x == 0 && t < HD) { g_cs[HD + t] = 0.f; g_cq[HD + t] = 0.f; }
    if (t < HD) {
        float invN = 1.0f / (float)N;
        float m = g_cs[t] * invN;                       // layer-1 stats (buf0)
        float v = fmaf(-m, m, g_cq[t] * invN);
        float sc = gam[t] * rsqrtf(v + 1e-5f);
        ssc[t] = sc;
        ssh[t] = fmaf(-m, sc, bet[t]);
    }
    __syncthreads();

    int gt = blockIdx.x * blockDim.x + t;
    int w = gt >> 5, lane = gt & 31;
    if (w >= N) return;

    float scr[8], shr[8];
#pragma unroll
    for (int j = 0; j < 8; j++) { scr[j] = ssc[lane * 8 + j]; shr[j] = ssh[lane * 8 + j]; }

    const uint4* xp = (const uint4*)h1;
    float acc[8];
    {
        uint4 s = xp[(size_t)w * 32 + lane];
        float2 a = __half22float2(*(const __half2*)&s.x);
        float2 b = __half22float2(*(const __half2*)&s.y);
        float2 c = __half22float2(*(const __half2*)&s.z);
        float2 d = __half22float2(*(const __half2*)&s.w);
        acc[0] = fmaxf(fmaf(a.x, scr[0], shr[0]), 0.f);
        acc[1] = fmaxf(fmaf(a.y, scr[1], shr[1]), 0.f);
        acc[2] = fmaxf(fmaf(b.x, scr[2], shr[2]), 0.f);
        acc[3] = fmaxf(fmaf(b.y, scr[3], shr[3]), 0.f);
        acc[4] = fmaxf(fmaf(c.x, scr[4], shr[4]), 0.f);
        acc[5] = fmaxf(fmaf(c.y, scr[5], shr[5]), 0.f);
        acc[6] = fmaxf(fmaf(d.x, scr[6], shr[6]), 0.f);
        acc[7] = fmaxf(fmaf(d.y, scr[7], shr[7]), 0.f);
    }
    int e = g_off[w], e1 = g_off[w + 1];
    for (; e + 7 < e1; e += 8) {
        uint4 s[8];
#pragma unroll
        for (int u = 0; u < 8; u++) s[u] = xp[(size_t)g_nbr[e + u] * 32 + lane];
#pragma unroll
        for (int u = 0; u < 8; u++) {
            float2 v;
            v = __half22float2(*(const __half2*)&s[u].x);
            acc[0] += fmaxf(fmaf(v.x, scr[0], shr[0]), 0.f);
            acc[1] += fmaxf(fmaf(v.y, scr[1], shr[1]), 0.f);
            v = __half22float2(*(const __half2*)&s[u].y);
            acc[2] += fmaxf(fmaf(v.x, scr[2], shr[2]), 0.f);
            acc[3] += fmaxf(fmaf(v.y, scr[3], shr[3]), 0.f);
            v = __half22float2(*(const __half2*)&s[u].z);
            acc[4] += fmaxf(fmaf(v.x, scr[4], shr[4]), 0.f);
            acc[5] += fmaxf(fmaf(v.y, scr[5], shr[5]), 0.f);
            v = __half22float2(*(const __half2*)&s[u].w);
            acc[6] += fmaxf(fmaf(v.x, scr[6], shr[6]), 0.f);
            acc[7] += fmaxf(fmaf(v.y, scr[7], shr[7]), 0.f);
        }
    }
    for (; e < e1; e++) {
        uint4 s = xp[(size_t)g_nbr[e] * 32 + lane];
        float2 v;
        v = __half22float2(*(const __half2*)&s.x);
        acc[0] += fmaxf(fmaf(v.x, scr[0], shr[0]), 0.f);
        acc[1] += fmaxf(fmaf(v.y, scr[1], shr[1]), 0.f);
        v = __half22float2(*(const __half2*)&s.y);
        acc[2] += fmaxf(fmaf(v.x, scr[2], shr[2]), 0.f);
        acc[3] += fmaxf(fmaf(v.y, scr[3], shr[3]), 0.f);
        v = __half22float2(*(const __half2*)&s.z);
        acc[4] += fmaxf(fmaf(v.x, scr[4], shr[4]), 0.f);
        acc[5] += fmaxf(fmaf(v.y, scr[5], shr[5]), 0.f);
        v = __half22float2(*(const __half2*)&s.w);
        acc[6] += fmaxf(fmaf(v.x, scr[6], shr[6]), 0.f);
        acc[7] += fmaxf(fmaf(v.y, scr[7], shr[7]), 0.f);
    }
    __half2 p0 = __floats2half2_rn(acc[0], acc[1]);
    __half2 p1 = __floats2half2_rn(acc[2], acc[3]);
    __half2 p2 = __floats2half2_rn(acc[4], acc[5]);
    __half2 p3 = __floats2half2_rn(acc[6], acc[7]);
    uint4 pk;
    pk.x = *(uint32_t*)&p0; pk.y = *(uint32_t*)&p1;
    pk.z = *(uint32_t*)&p2; pk.w = *(uint32_t*)&p3;
    ((uint4*)out)[(size_t)w * 32 + lane] = pk;
}

// ---------------- layer-3 gather (plain, on xb); zeros stats buf0 ----------------
__global__ void k_gather256h(const __half* __restrict__ xin, __half* __restrict__ out, int N)
{
    if (blockIdx.x == 0 && threadIdx.x < HD) { g_cs[threadIdx.x] = 0.f; g_cq[threadIdx.x] = 0.f; }
    int gt = blockIdx.x * blockDim.x + threadIdx.x;
    int w = gt >> 5, lane = gt & 31;
    if (w >= N) return;
    const uint4* xp = (const uint4*)xin;
    float acc[8];
    {
        uint4 s = xp[(size_t)w * 32 + lane];
        float2 a = __half22float2(*(const __half2*)&s.x);
        float2 b = __half22float2(*(const __half2*)&s.y);
        float2 c = __half22float2(*(const __half2*)&s.z);
        float2 d = __half22float2(*(const __half2*)&s.w);
        acc[0] = a.x; acc[1] = a.y; acc[2] = b.x; acc[3] = b.y;
        acc[4] = c.x; acc[5] = c.y; acc[6] = d.x; acc[7] = d.y;
    }
    int e = g_off[w], e1 = g_off[w + 1];
    for (; e + 7 < e1; e += 8) {
        uint4 s[8];
#pragma unroll
        for (int u = 0; u < 8; u++) s[u] = xp[(size_t)g_nbr[e + u] * 32 + lane];
#pragma unroll
        for (int u = 0; u < 8; u++) {
            float2 v;
            v = __half22float2(*(const __half2*)&s[u].x); acc[0] += v.x; acc[1] += v.y;
            v = __half22float2(*(const __half2*)&s[u].y); acc[2] += v.x; acc[3] += v.y;
            v = __half22float2(*(const __half2*)&s[u].z); acc[4] += v.x; acc[5] += v.y;
            v = __half22float2(*(const __half2*)&s[u].w); acc[6] += v.x; acc[7] += v.y;
        }
    }
    for (; e < e1; e++) {
        uint4 s = xp[(size_t)g_nbr[e] * 32 + lane];
        float2 a = __half22float2(*(const __half2*)&s.x);
        float2 b = __half22float2(*(const __half2*)&s.y);
        float2 c = __half22float2(*(const __half2*)&s.z);
        float2 d = __half22float2(*(const __half2*)&s.w);
        acc[0] += a.x; acc[1] += a.y; acc[2] += b.x; acc[3] += b.y;
        acc[4] += c.x; acc[5] += c.y; acc[6] += d.x; acc[7] += d.y;
    }
    __half2 p0 = __floats2half2_rn(acc[0], acc[1]);
    __half2 p1 = __floats2half2_rn(acc[2], acc[3]);
    __half2 p2 = __floats2half2_rn(acc[4], acc[5]);
    __half2 p3 = __floats2half2_rn(acc[6], acc[7]);
    uint4 pk;
    pk.x = *(uint32_t*)&p0; pk.y = *(uint32_t*)&p1;
    pk.z = *(uint32_t*)&p2; pk.w = *(uint32_t*)&p3;
    ((uint4*)out)[(size_t)w * 32 + lane] = pk;
}

// ---------------- fp16 mma GEMM: 3-stage cp.async pipeline (R11 proven) ----------------
template <int K>
__launch_bounds__(256, 2)
__global__ void k_gemm(const __half* __restrict__ A, const __half* __restrict__ Wt,
                       const float* __restrict__ bias, __half* __restrict__ Hout,
                       float* __restrict__ cs, float* __restrict__ cq, int M)
{
    const int BK = 32, NIT = K / BK, LDA = 40;
    const int STG = 2 * 128 * LDA * 2;
    extern __shared__ char dsm[];
    float* RedS = (float*)dsm;
    float* RedQ = (float*)(dsm + 512);
    uint32_t tbase = (uint32_t)__cvta_generic_to_shared(dsm + 1024);

    int bm = blockIdx.x * 128, bn = blockIdx.y * 128;
    int t = threadIdx.x, lane = t & 31, w = t >> 5;
    int m_warp = (w & 1) * 64;
    int n_warp = (w >> 1) * 32;

    if (t < 128) { RedS[t] = 0.f; RedQ[t] = 0.f; }

    int r0 = t >> 2, s0 = (t & 3) * 8;
    int r1 = r0 + 64;
    int gA0 = bm + r0, gA1 = bm + r1;
    int az0 = (gA0 < M) ? 16 : 0, az1 = (gA1 < M) ? 16 : 0;
    const __half* apB0 = A + (size_t)gA0 * K + s0;
    const __half* apB1 = A + (size_t)gA1 * K + s0;
    const __half* bpB0 = Wt + (size_t)(bn + r0) * K + s0;
    const __half* bpB1 = Wt + (size_t)(bn + r1) * K + s0;
    uint32_t dA0 = (uint32_t)((r0 * LDA + s0) * 2);
    uint32_t dA1 = (uint32_t)((r1 * LDA + s0) * 2);
    uint32_t dB0 = (uint32_t)(128 * LDA * 2) + dA0;
    uint32_t dB1 = (uint32_t)(128 * LDA * 2) + dA1;

    uint32_t offA[4], offB[2];
#pragma unroll
    for (int mt = 0; mt < 4; mt++)
        offA[mt] = (uint32_t)(((m_warp + mt * 16 + (lane & 15)) * LDA + (lane >> 4) * 8) * 2);
#pragma unroll
    for (int p = 0; p < 2; p++)
        offB[p] = (uint32_t)(128 * LDA * 2)
                + (uint32_t)(((n_warp + p * 16 + (lane & 7) + (lane >> 4) * 8) * LDA
                             + ((lane >> 3) & 1) * 8) * 2);

    float acc[4][4][4];
#pragma unroll
    for (int mt = 0; mt < 4; mt++)
#pragma unroll
        for (int nt = 0; nt < 4; nt++)
#pragma unroll
            for (int f = 0; f < 4; f++) acc[mt][nt][f] = 0.f;

#pragma unroll
    for (int pt = 0; pt < 2; pt++) {
        uint32_t sb = tbase + (uint32_t)pt * STG;
        int k0 = pt * BK;
        cp16s(sb + dA0, apB0 + k0, az0);
        cp16s(sb + dA1, apB1 + k0, az1);
        cp16s(sb + dB0, bpB0 + k0, 16);
        cp16s(sb + dB1, bpB1 + k0, 16);
        CP_COMMIT();
    }

#pragma unroll
    for (int it = 0; it < NIT; it++) {
        if (it < NIT - 1) CP_WAIT1(); else CP_WAIT0();
        __syncthreads();
        uint32_t sb = tbase + (uint32_t)(it % 3) * STG;
#pragma unroll
        for (int ks = 0; ks < 2; ks++) {
            uint32_t kb = (uint32_t)(ks * 16 * 2);
            uint32_t af[4][4], bf[4][2];
#pragma unroll
            for (int mt = 0; mt < 4; mt++)
                LDSM_X4(af[mt][0], af[mt][1], af[mt][2], af[mt][3], sb + offA[mt] + kb);
            LDSM_X4(bf[0][0], bf[0][1], bf[1][0], bf[1][1], sb + offB[0] + kb);
            LDSM_X4(bf[2][0], bf[2][1], bf[3][0], bf[3][1], sb + offB[1] + kb);
#pragma unroll
            for (int mt = 0; mt < 4; mt++)
#pragma unroll
                for (int nt = 0; nt < 4; nt++)
                    MMA_F16(acc[mt][nt], af[mt], bf[nt]);
        }
        if (it + 2 < NIT) {
            uint32_t sn = tbase + (uint32_t)((it + 2) % 3) * STG;
            int k0 = (it + 2) * BK;
            cp16s(sn + dA0, apB0 + k0, az0);
            cp16s(sn + dA1, apB1 + k0, az1);
            cp16s(sn + dB0, bpB0 + k0, 16);
            cp16s(sn + dB1, bpB1 + k0, 16);
            CP_COMMIT();
        }
    }
    __syncthreads();

    int ar = lane >> 2;
    int ac2 = (lane & 3) * 2;
#pragma unroll
    for (int nt = 0; nt < 4; nt++) {
        int cc = n_warp + nt * 8 + ac2;
        float b0 = bias[bn + cc], b1 = bias[bn + cc + 1];
        float s0a = 0.f, q0 = 0.f, s1a = 0.f, q1 = 0.f;
#pragma unroll
        for (int mt = 0; mt < 4; mt++) {
            int gr0 = bm + m_warp + mt * 16 + ar;
            int gr1 = gr0 + 8;
            if (gr0 < M) {
                float o0 = acc[mt][nt][0] + b0;
                float o1 = acc[mt][nt][1] + b1;
                *(__half2*)(Hout + (size_t)gr0 * HD + bn + cc) = __floats2half2_rn(o0, o1);
                s0a += o0; q0 += o0 * o0; s1a += o1; q1 += o1 * o1;
            }
            if (gr1 < M) {
                float o2 = acc[mt][nt][2] + b0;
                float o3 = acc[mt][nt][3] + b1;
                *(__half2*)(Hout + (size_t)gr1 * HD + bn + cc) = __floats2half2_rn(o2, o3);
                s0a += o2; q0 += o2 * o2; s1a += o3; q1 += o3 * o3;
            }
        }
        atomicAdd(&RedS[cc], s0a);
        atomicAdd(&RedQ[cc], q0);
        atomicAdd(&RedS[cc + 1], s1a);
        atomicAdd(&RedQ[cc + 1], q1);
    }
    __syncthreads();
    if (t < 128) {
        atomicAdd(&cs[bn + t], RedS[t]);
        atomicAdd(&cq[bn + t], RedQ[t]);
    }
}

// ---------------- fused layer-2 elementwise: xb = relu(bn2(h2)) + relu(bn1(h1)) ----------------
__global__ void k_bnrelu2f(const __half* __restrict__ H1, const __half* __restrict__ H2,
                           const float* __restrict__ g1, const float* __restrict__ b1,
                           const float* __restrict__ g2, const float* __restrict__ b2,
                           __half* __restrict__ out, int M)
{
    __shared__ float sc1[HD], sh1[HD], sc2[HD], sh2[HD];
    int t = threadIdx.x;
    if (blockIdx.x < 64) {
        g_pool[blockIdx.x * 256 + t] = 0.f;
        if (blockIdx.x == 0 && t < NGR) g_cnt[t] = 0.f;
    }
    if (t < HD) {
        float invN = 1.0f / (float)M;
        float m1 = g_cs[t] * invN;
        float v1 = fmaf(-m1, m1, g_cq[t] * invN);
        float s1 = g1[t] * rsqrtf(v1 + 1e-5f);
        sc1[t] = s1; sh1[t] = fmaf(-m1, s1, b1[t]);
        float m2 = g_cs[HD + t] * invN;
        float v2 = fmaf(-m2, m2, g_cq[HD + t] * invN);
        float s2 = g2[t] * rsqrtf(v2 + 1e-5f);
        sc2[t] = s2; sh2[t] = fmaf(-m2, s2, b2[t]);
    }
    __syncthreads();

    int idx = blockIdx.x * blockDim.x + t;
    if (idx >= M * 32) return;
    int c8 = (idx & 31) * 8;
    uint4 u1 = ((const uint4*)H1)[idx];
    uint4 u2 = ((const uint4*)H2)[idx];
    const __half2* p1 = (const __half2*)&u1;
    const __half2* p2 = (const __half2*)&u2;
    float o[8];
#pragma unroll
    for (int q = 0; q < 4; q++) {
        float2 a = __half22float2(p1[q]);
        float2 b = __half22float2(p2[q]);
        int c = c8 + q * 2;
        o[q * 2]     = fmaxf(fmaf(b.x, sc2[c], sh2[c]), 0.f)
                     + fmaxf(fmaf(a.x, sc1[c], sh1[c]), 0.f);
        o[q * 2 + 1] = fmaxf(fmaf(b.y, sc2[c + 1], sh2[c + 1]), 0.f)
                     + fmaxf(fmaf(a.y, sc1[c + 1], sh1[c + 1]), 0.f);
    }
    __half2 q0 = __floats2half2_rn(o[0], o[1]);
    __half2 q1 = __floats2half2_rn(o[2], o[3]);
    __half2 q2 = __floats2half2_rn(o[4], o[5]);
    __half2 q3 = __floats2half2_rn(o[6], o[7]);
    uint4 pk;
    pk.x = *(uint32_t*)&q0; pk.y = *(uint32_t*)&q1;
    pk.z = *(uint32_t*)&q2; pk.w = *(uint32_t*)&q3;
    ((uint4*)out)[idx] = pk;
}

// ---------------- fused layer-3 elementwise: x3 = relu(bn3(h3)) + xb ----------------
__global__ void k_bnrelu3f(const __half* __restrict__ H3, const __half* __restrict__ resid,
                           const float* __restrict__ g3, const float* __restrict__ b3,
                           __half* __restrict__ out, int M)
{
    __shared__ float sc3[HD], sh3[HD];
    int t = threadIdx.x;
    if (t < HD) {
        float invN = 1.0f / (float)M;
        float m = g_cs[t] * invN;                      // layer-3 stats (buf0)
        float v = fmaf(-m, m, g_cq[t] * invN);
        float s = g3[t] * rsqrtf(v + 1e-5f);
        sc3[t] = s; sh3[t] = fmaf(-m, s, b3[t]);
    }
    __syncthreads();

    int idx = blockIdx.x * blockDim.x + t;
    if (idx >= M * 32) return;
    int c8 = (idx & 31) * 8;
    uint4 u3 = ((const uint4*)H3)[idx];
    uint4 ur = ((const uint4*)resid)[idx];
    const __half2* p3 = (const __half2*)&u3;
    const __half2* pr = (const __half2*)&ur;
    float o[8];
#pragma unroll
    for (int q = 0; q < 4; q++) {
        float2 a = __half22float2(p3[q]);
        float2 r = __half22float2(pr[q]);
        int c = c8 + q * 2;
        o[q * 2]     = fmaxf(fmaf(a.x, sc3[c], sh3[c]), 0.f) + r.x;
        o[q * 2 + 1] = fmaxf(fmaf(a.y, sc3[c + 1], sh3[c + 1]), 0.f) + r.y;
    }
    __half2 q0 = __floats2half2_rn(o[0], o[1]);
    __half2 q1 = __floats2half2_rn(o[2], o[3]);
    __half2 q2 = __floats2half2_rn(o[4], o[5]);
    __half2 q3 = __floats2half2_rn(o[6], o[7]);
    uint4 pk;
    pk.x = *(uint32_t*)&q0; pk.y = *(uint32_t*)&q1;
    pk.z = *(uint32_t*)&q2; pk.w = *(uint32_t*)&q3;
    ((uint4*)out)[idx] = pk;
}

// ---------------- pool: batch sorted -> register-accumulate, flush on change ----------------
__global__ void k_pool2(const __half* __restrict__ x3, int N)
{
    __shared__ int sb[128];
    int n0 = blockIdx.x * 128;
    int n1 = n0 + 128; if (n1 > N) n1 = N;
    int t = threadIdx.x;
    if (t < n1 - n0) sb[t] = g_batch[n0 + t];
    __syncthreads();
    if (n1 <= n0) return;
    float acc = 0.f;
    int curg = sb[0], cnt = 0;
    for (int n = n0; n < n1; n++) {
        int g = sb[n - n0];
        if (g != curg) {
            atomicAdd(&g_pool[curg * HD + t], acc);
            if (t == 0) atomicAdd(&g_cnt[curg], (float)cnt);
            acc = 0.f; cnt = 0; curg = g;
        }
        acc += __half2float(x3[(size_t)n * HD + t]);
        cnt++;
    }
    atomicAdd(&g_pool[curg * HD + t], acc);
    if (t == 0) atomicAdd(&g_cnt[curg], (float)cnt);
}

// ---------------- final MLP head (64 graphs) ----------------
__global__ void k_final(const float* __restrict__ fcW1, const float* __restrict__ fcb1,
                        const float* __restrict__ fcW2, const float* __restrict__ fcb2,
                        float* __restrict__ out)
{
    __shared__ float prow[HD];
    __shared__ float hred[HD];
    int g = blockIdx.x, t = threadIdx.x;
    float cnt = fmaxf(g_cnt[g], 1.0f);
    prow[t] = g_pool[g * HD + t] / cnt;
    __syncthreads();
    float acc = fcb1[t];
    for (int k = 0; k < HD; k++)
        acc = fmaf(prow[k], __ldg(fcW1 + (size_t)k * HD + t), acc);
    float h = fmaxf(acc, 0.0f);
    hred[t] = h * fcW2[t];
    __syncthreads();
    for (int s = HD / 2; s > 0; s >>= 1) {
        if (t < s) hred[t] += hred[t + s];
        __syncthreads();
    }
    if (t == 0) out[g] = hred[0] + fcb2[0];
}

// ---------------- launch ----------------
extern "C" void kernel_launch(void* const* d_in, const int* in_sizes, int n_in,
                              void* d_out, int out_size)
{
    int base = 3;
    if (n_in >= 20 && in_sizes[3] == 1) base = 4;

    const float* x   = (const float*)d_in[0];
    const int*   ei  = (const int*)d_in[1];
    const int*   bat = (const int*)d_in[2];
    const float* W1  = (const float*)d_in[base + 0];
    const float* b1  = (const float*)d_in[base + 1];
    const float* W2  = (const float*)d_in[base + 2];
    const float* b2  = (const float*)d_in[base + 3];
    const float* W3  = (const float*)d_in[base + 4];
    const float* b3  = (const float*)d_in[base + 5];
    const float* ga1 = (const float*)d_in[base + 6];
    const float* be1 = (const float*)d_in[base + 7];
    const float* ga2 = (const float*)d_in[base + 8];
    const float* be2 = (const float*)d_in[base + 9];
    const float* ga3 = (const float*)d_in[base + 10];
    const float* be3 = (const float*)d_in[base + 11];
    const float* fcW1 = (const float*)d_in[base + 12];
    const float* fcb1 = (const float*)d_in[base + 13];
    const float* fcW2 = (const float*)d_in[base + 14];
    const float* fcb2 = (const float*)d_in[base + 15];

    int N = in_sizes[0] / 128;
    int E = in_sizes[1] / 2;

    void* p;
    __half *aggh, *xah, *xbh, *w1t, *w2t, *w3t, *ha, *hb;
    float *cs, *cq;
    cudaGetSymbolAddress(&p, g_aggh); aggh = (__half*)p;
    cudaGetSymbolAddress(&p, g_hbuf); ha   = (__half*)p; hb = ha + (size_t)NMAX * HD;
    cudaGetSymbolAddress(&p, g_xah);  xah  = (__half*)p;
    cudaGetSymbolAddress(&p, g_xbh);  xbh  = (__half*)p;
    cudaGetSymbolAddress(&p, g_w1t);  w1t  = (__half*)p;
    cudaGetSymbolAddress(&p, g_w2t);  w2t  = (__half*)p;
    cudaGetSymbolAddress(&p, g_w3t);  w3t  = (__half*)p;
    cudaGetSymbolAddress(&p, g_cs);   cs   = (float*)p;
    cudaGetSymbolAddress(&p, g_cq);   cq   = (float*)p;

    const int SHM = 1024 + 3 * 20480;
    cudaFuncSetAttribute(k_gemm<128>, cudaFuncAttributeMaxDynamicSharedMemorySize, SHM);
    cudaFuncSetAttribute(k_gemm<256>, cudaFuncAttributeMaxDynamicSharedMemorySize, SHM);

    const int tb = 256;
    int ebl = (E + tb - 1) / tb;
    int nb256 = (N + 255) / 256;
    int wbl = (N * 32 + tb - 1) / tb;
    int bnbl = (N * 32 + tb - 1) / tb;
    int nx = (N * 32 + 255) / 256;
    dim3 ggrid((N + 127) / 128, 2);

    // CSR + prep (fused)
    k_convprep<<<ebl + nx + 768, tb>>>(ei, bat, x, W1, W2, W3, E, N, ebl, nx);
    k_bsum<<<nb256, 256>>>(N);
    k_off<<<nb256, 256>>>(N);
    k_fill<<<ebl, tb>>>(E);

    // layer 1: gather (zeros stats0) -> gemm1 -> h_a (stats in buf0)
    k_gather128h<<<wbl, tb>>>(aggh, N);
    k_gemm<128><<<ggrid, 256, SHM>>>(aggh, w1t, b1, ha, cs, cq, N);

    // layer 2: fused-BN1 gather on h_a (zeros stats1) -> gemm2 -> h_b (stats buf1)
    k_gather256bn<<<wbl, tb>>>(ha, aggh, ga1, be1, N);
    k_gemm<256><<<ggrid, 256, SHM>>>(aggh, w2t, b2, hb, cs + HD, cq + HD, N);

    // xb = relu(bn2(h_b)) + relu(bn1(h_a))
    k_bnrelu2f<<<bnbl, tb>>>(ha, hb, ga1, be1, ga2, be2, xbh, N);

    // layer 3: gather on xb (zeros stats0) -> gemm3 -> h_a reused as h3 (stats buf0)
    k_gather256h<<<wbl, tb>>>(xbh, aggh, N);
    k_gemm<256><<<ggrid, 256, SHM>>>(aggh, w3t, b3, ha, cs, cq, N);

    // x3 = relu(bn3(h3)) + xb
    k_bnrelu3f<<<bnbl, tb>>>(ha, xbh, ga3, be3, xah, N);

    // pool + head
    k_pool2<<<(N + 127) / 128, 256>>>(xah, N);
    k_final<<<NGR, 256>>>(fcW1, fcb1, fcW2, fcb2, (float*)d_out);
}

// round 16
// speedup vs baseline: 1.3183x; 1.0119x over previous
#include <cuda_runtime.h>
#include <cuda_fp16.h>
#include <stdint.h>

#define HD 256
#define NMAX 50048
#define EMAX 800000
#define NGR 64

// ---------------- device scratch (static, no runtime alloc) ----------------
__device__ __half g_aggh[(size_t)NMAX * HD];
__device__ float  g_hbuf[(size_t)NMAX * HD];   // holds TWO fp16 buffers: h_a, h_b
__device__ __half g_x16 [(size_t)NMAX * 128];
__device__ __half g_xbh [(size_t)NMAX * HD];   // xb (layer-2 output)
__device__ __half g_w1t [128 * 256];           // [n][k] fp16 transposed
__device__ __half g_w2t [256 * 256];
__device__ __half g_w3t [256 * 256];
__device__ int    g_src [EMAX];
__device__ int    g_dstv[EMAX];
__device__ int    g_nbr [EMAX];
__device__ int    g_deg [NMAX];
__device__ int    g_off [NMAX + 1];
__device__ int    g_cur [NMAX];
__device__ int    g_batch[NMAX];
__device__ int    g_bsum[1024];
__device__ float  g_cs[2 * HD];                // stats ping-pong: buf0 / buf1
__device__ float  g_cq[2 * HD];
__device__ float  g_pool[NGR * HD];
__device__ float  g_cnt [NGR];

// ---------------- cp.async helpers ----------------
__device__ __forceinline__ void cp16s(uint32_t saddr, const void* g, int sz)
{
    asm volatile("cp.async.cg.shared.global [%0], [%1], 16, %2;" :: "r"(saddr), "l"(g), "r"(sz));
}
#define CP_COMMIT() asm volatile("cp.async.commit_group;")
#define CP_WAIT1()  asm volatile("cp.async.wait_group 1;")
#define CP_WAIT0()  asm volatile("cp.async.wait_group 0;")

#define LDSM_X4(r0, r1, r2, r3, addr)                                        \
    asm volatile("ldmatrix.sync.aligned.m8n8.x4.shared.b16 {%0,%1,%2,%3}, [%4];" \
                 : "=r"(r0), "=r"(r1), "=r"(r2), "=r"(r3) : "r"(addr))

#define MMA_F16(d, a, b)                                                          \
    asm volatile("mma.sync.aligned.m16n8k16.row.col.f32.f16.f16.f32 "            \
                 "{%0,%1,%2,%3}, {%4,%5,%6,%7}, {%8,%9}, {%0,%1,%2,%3};"         \
                 : "+f"(d[0]), "+f"(d[1]), "+f"(d[2]), "+f"(d[3])                 \
                 : "r"(a[0]), "r"(a[1]), "r"(a[2]), "r"(a[3]),                    \
                   "r"(b[0]), "r"(b[1]))

// ---------------- fused convert + x2h + weight transpose ----------------
__global__ void k_convprep(const int* __restrict__ ei, const int* __restrict__ bat,
                           const float* __restrict__ x,
                           const float* __restrict__ W1, const float* __restrict__ W2,
                           const float* __restrict__ W3, int E, int N, int ebl, int nx)
{
    int b = blockIdx.x, t = threadIdx.x;
    if (b < ebl) {
        int e64 = (ei[1] == 0 && ei[3] == 0 && ei[5] == 0 && ei[7] == 0) ? 1 : 0;
        int w = N - 1; if (!(w & 1)) w--;
        int b64 = (bat[w] == 0) ? 1 : 0;
        int i = b * 256 + t;
        if (i < E) {
            int s, d;
            if (e64) { s = ei[2 * i]; d = ei[2 * (E + i)]; }
            else     { s = ei[i];     d = ei[E + i]; }
            g_src[i] = s; g_dstv[i] = d;
            atomicAdd(&g_deg[d], 1);
        }
        if (i < N) g_batch[i] = b64 ? bat[2 * i] : bat[i];
    } else if (b < ebl + nx) {
        int i = (b - ebl) * 256 + t;
        if (i < N * 32) {
            float4 v = ((const float4*)x)[i];
            __half2* o = (__half2*)g_x16;
            o[2 * i]     = __floats2half2_rn(v.x, v.y);
            o[2 * i + 1] = __floats2half2_rn(v.z, v.w);
        }
    } else {
        int wb = b - ebl - nx;
        const float* W = (wb < 256) ? W1 : ((wb < 512) ? W2 : W3);
        __half* Wt = (wb < 256) ? g_w1t : ((wb < 512) ? g_w2t : g_w3t);
        int K = (wb < 256) ? 128 : 256;
        int n = wb & 255;
        for (int k = t; k < K; k += 256)
            Wt[(size_t)n * K + k] = __float2half(W[(size_t)k * HD + n]);
    }
}

// ---------------- CSR scan pipeline ----------------
__global__ void k_bsum(int N)
{
    int t = threadIdx.x;
    int i = blockIdx.x * 256 + t;
    int v = (i < N) ? g_deg[i] : 0;
#pragma unroll
    for (int o = 16; o; o >>= 1) v += __shfl_down_sync(~0u, v, o);
    __shared__ int ws[8];
    if ((t & 31) == 0) ws[t >> 5] = v;
    __syncthreads();
    if (t == 0) {
        int s = 0;
#pragma unroll
        for (int k = 0; k < 8; k++) s += ws[k];
        g_bsum[blockIdx.x] = s;
    }
}

__global__ void k_off(int N)
{
    __shared__ int ws[8];
    __shared__ int s_bpre;
    int t = threadIdx.x;
    int lane = t & 31, wid = t >> 5;

    int bv = (t < blockIdx.x) ? g_bsum[t] : 0;
#pragma unroll
    for (int o = 16; o; o >>= 1) bv += __shfl_down_sync(~0u, bv, o);
    if (lane == 0) ws[wid] = bv;
    __syncthreads();
    if (t == 0) {
        int s = 0;
#pragma unroll
        for (int k = 0; k < 8; k++) s += ws[k];
        s_bpre = s;
    }
    __syncthreads();

    int i = blockIdx.x * 256 + t;
    int v = (i < N) ? g_deg[i] : 0;
    int x = v;
#pragma unroll
    for (int o = 1; o < 32; o <<= 1) {
        int y = __shfl_up_sync(~0u, x, o);
        if (lane >= o) x += y;
    }
    __syncthreads();
    if (lane == 31) ws[wid] = x;
    __syncthreads();
    if (t < 8) {
        int y = ws[t];
#pragma unroll
        for (int o = 1; o < 8; o <<= 1) {
            int z = __shfl_up_sync(0xff, y, o);
            if (t >= o) y += z;
        }
        ws[t] = y;
    }
    __syncthreads();
    int incl = x + (wid ? ws[wid - 1] : 0);
    int off = s_bpre + incl - v;
    if (i < N) {
        g_off[i] = off;
        g_cur[i] = off;
        g_deg[i] = 0;
    }
    if (i == N - 1) g_off[N] = off + v;
}

__global__ void k_fill(int E)
{
    int i = blockIdx.x * blockDim.x + threadIdx.x;
    if (i < E) {
        int d = g_dstv[i];
        int p = atomicAdd(&g_cur[d], 1);
        g_nbr[p] = g_src[i];
    }
}

// ---------------- layer-1 gather (fp16 x, zeros stats buf0), unroll-8 ----------------
__global__ void k_gather128h(__half* __restrict__ out, int N)
{
    if (blockIdx.x == 0 && threadIdx.x < HD) { g_cs[threadIdx.x] = 0.f; g_cq[threadIdx.x] = 0.f; }
    int gt = blockIdx.x * blockDim.x + threadIdx.x;
    int w = gt >> 5, lane = gt & 31;
    if (w >= N) return;
    const uint2* xp = (const uint2*)g_x16;
    float acc[4];
    {
        uint2 s = xp[(size_t)w * 32 + lane];
        float2 a = __half22float2(*(const __half2*)&s.x);
        float2 b = __half22float2(*(const __half2*)&s.y);
        acc[0] = a.x; acc[1] = a.y; acc[2] = b.x; acc[3] = b.y;
    }
    int e = g_off[w], e1 = g_off[w + 1];
    for (; e + 7 < e1; e += 8) {
        uint2 s[8];
#pragma unroll
        for (int u = 0; u < 8; u++) s[u] = xp[(size_t)g_nbr[e + u] * 32 + lane];
#pragma unroll
        for (int u = 0; u < 8; u++) {
            float2 a = __half22float2(*(const __half2*)&s[u].x);
            float2 b = __half22float2(*(const __half2*)&s[u].y);
            acc[0] += a.x; acc[1] += a.y; acc[2] += b.x; acc[3] += b.y;
        }
    }
    for (; e < e1; e++) {
        uint2 s = xp[(size_t)g_nbr[e] * 32 + lane];
        float2 a = __half22float2(*(const __half2*)&s.x);
        float2 b = __half22float2(*(const __half2*)&s.y);
        acc[0] += a.x; acc[1] += a.y; acc[2] += b.x; acc[3] += b.y;
    }
    __half2 p0 = __floats2half2_rn(acc[0], acc[1]);
    __half2 p1 = __floats2half2_rn(acc[2], acc[3]);
    uint2 pk; pk.x = *(uint32_t*)&p0; pk.y = *(uint32_t*)&p1;
    ((uint2*)out)[(size_t)w * 32 + lane] = pk;
}

// ---------------- layer-2 gather with fused BN1+ReLU on raw h1; zeros stats buf1 ----------------
__global__ void k_gather256bn(const __half* __restrict__ h1, __half* __restrict__ out,
                              const float* __restrict__ gam, const float* __restrict__ bet,
                              int N)
{
    __shared__ float ssc[HD], ssh[HD];
    int t = threadIdx.x;
    if (blockIdx.x == 0 && t < HD) { g_cs[HD + t] = 0.f; g_cq[HD + t] = 0.f; }
    if (t < HD) {
        float invN = 1.0f / (float)N;
        float m = g_cs[t] * invN;
        float v = fmaf(-m, m, g_cq[t] * invN);
        float sc = gam[t] * rsqrtf(v + 1e-5f);
        ssc[t] = sc;
        ssh[t] = fmaf(-m, sc, bet[t]);
    }
    __syncthreads();

    int gt = blockIdx.x * blockDim.x + t;
    int w = gt >> 5, lane = gt & 31;
    if (w >= N) return;

    float scr[8], shr[8];
#pragma unroll
    for (int j = 0; j < 8; j++) { scr[j] = ssc[lane * 8 + j]; shr[j] = ssh[lane * 8 + j]; }

    const uint4* xp = (const uint4*)h1;
    float acc[8];
    {
        uint4 s = xp[(size_t)w * 32 + lane];
        float2 a = __half22float2(*(const __half2*)&s.x);
        float2 b = __half22float2(*(const __half2*)&s.y);
        float2 c = __half22float2(*(const __half2*)&s.z);
        float2 d = __half22float2(*(const __half2*)&s.w);
        acc[0] = fmaxf(fmaf(a.x, scr[0], shr[0]), 0.f);
        acc[1] = fmaxf(fmaf(a.y, scr[1], shr[1]), 0.f);
        acc[2] = fmaxf(fmaf(b.x, scr[2], shr[2]), 0.f);
        acc[3] = fmaxf(fmaf(b.y, scr[3], shr[3]), 0.f);
        acc[4] = fmaxf(fmaf(c.x, scr[4], shr[4]), 0.f);
        acc[5] = fmaxf(fmaf(c.y, scr[5], shr[5]), 0.f);
        acc[6] = fmaxf(fmaf(d.x, scr[6], shr[6]), 0.f);
        acc[7] = fmaxf(fmaf(d.y, scr[7], shr[7]), 0.f);
    }
    int e = g_off[w], e1 = g_off[w + 1];
    for (; e + 7 < e1; e += 8) {
        uint4 s[8];
#pragma unroll
        for (int u = 0; u < 8; u++) s[u] = xp[(size_t)g_nbr[e + u] * 32 + lane];
#pragma unroll
        for (int u = 0; u < 8; u++) {
            float2 v;
            v = __half22float2(*(const __half2*)&s[u].x);
            acc[0] += fmaxf(fmaf(v.x, scr[0], shr[0]), 0.f);
            acc[1] += fmaxf(fmaf(v.y, scr[1], shr[1]), 0.f);
            v = __half22float2(*(const __half2*)&s[u].y);
            acc[2] += fmaxf(fmaf(v.x, scr[2], shr[2]), 0.f);
            acc[3] += fmaxf(fmaf(v.y, scr[3], shr[3]), 0.f);
            v = __half22float2(*(const __half2*)&s[u].z);
            acc[4] += fmaxf(fmaf(v.x, scr[4], shr[4]), 0.f);
            acc[5] += fmaxf(fmaf(v.y, scr[5], shr[5]), 0.f);
            v = __half22float2(*(const __half2*)&s[u].w);
            acc[6] += fmaxf(fmaf(v.x, scr[6], shr[6]), 0.f);
            acc[7] += fmaxf(fmaf(v.y, scr[7], shr[7]), 0.f);
        }
    }
    for (; e < e1; e++) {
        uint4 s = xp[(size_t)g_nbr[e] * 32 + lane];
        float2 v;
        v = __half22float2(*(const __half2*)&s.x);
        acc[0] += fmaxf(fmaf(v.x, scr[0], shr[0]), 0.f);
        acc[1] += fmaxf(fmaf(v.y, scr[1], shr[1]), 0.f);
        v = __half22float2(*(const __half2*)&s.y);
        acc[2] += fmaxf(fmaf(v.x, scr[2], shr[2]), 0.f);
        acc[3] += fmaxf(fmaf(v.y, scr[3], shr[3]), 0.f);
        v = __half22float2(*(const __half2*)&s.z);
        acc[4] += fmaxf(fmaf(v.x, scr[4], shr[4]), 0.f);
        acc[5] += fmaxf(fmaf(v.y, scr[5], shr[5]), 0.f);
        v = __half22float2(*(const __half2*)&s.w);
        acc[6] += fmaxf(fmaf(v.x, scr[6], shr[6]), 0.f);
        acc[7] += fmaxf(fmaf(v.y, scr[7], shr[7]), 0.f);
    }
    __half2 p0 = __floats2half2_rn(acc[0], acc[1]);
    __half2 p1 = __floats2half2_rn(acc[2], acc[3]);
    __half2 p2 = __floats2half2_rn(acc[4], acc[5]);
    __half2 p3 = __floats2half2_rn(acc[6], acc[7]);
    uint4 pk;
    pk.x = *(uint32_t*)&p0; pk.y = *(uint32_t*)&p1;
    pk.z = *(uint32_t*)&p2; pk.w = *(uint32_t*)&p3;
    ((uint4*)out)[(size_t)w * 32 + lane] = pk;
}

// ---------------- layer-3 gather (plain, on xb); zeros stats buf0 ----------------
__global__ void k_gather256h(const __half* __restrict__ xin, __half* __restrict__ out, int N)
{
    if (blockIdx.x == 0 && threadIdx.x < HD) { g_cs[threadIdx.x] = 0.f; g_cq[threadIdx.x] = 0.f; }
    int gt = blockIdx.x * blockDim.x + threadIdx.x;
    int w = gt >> 5, lane = gt & 31;
    if (w >= N) return;
    const uint4* xp = (const uint4*)xin;
    float acc[8];
    {
        uint4 s = xp[(size_t)w * 32 + lane];
        float2 a = __half22float2(*(const __half2*)&s.x);
        float2 b = __half22float2(*(const __half2*)&s.y);
        float2 c = __half22float2(*(const __half2*)&s.z);
        float2 d = __half22float2(*(const __half2*)&s.w);
        acc[0] = a.x; acc[1] = a.y; acc[2] = b.x; acc[3] = b.y;
        acc[4] = c.x; acc[5] = c.y; acc[6] = d.x; acc[7] = d.y;
    }
    int e = g_off[w], e1 = g_off[w + 1];
    for (; e + 7 < e1; e += 8) {
        uint4 s[8];
#pragma unroll
        for (int u = 0; u < 8; u++) s[u] = xp[(size_t)g_nbr[e + u] * 32 + lane];
#pragma unroll
        for (int u = 0; u < 8; u++) {
            float2 v;
            v = __half22float2(*(const __half2*)&s[u].x); acc[0] += v.x; acc[1] += v.y;
            v = __half22float2(*(const __half2*)&s[u].y); acc[2] += v.x; acc[3] += v.y;
            v = __half22float2(*(const __half2*)&s[u].z); acc[4] += v.x; acc[5] += v.y;
            v = __half22float2(*(const __half2*)&s[u].w); acc[6] += v.x; acc[7] += v.y;
        }
    }
    for (; e < e1; e++) {
        uint4 s = xp[(size_t)g_nbr[e] * 32 + lane];
        float2 a = __half22float2(*(const __half2*)&s.x);
        float2 b = __half22float2(*(const __half2*)&s.y);
        float2 c = __half22float2(*(const __half2*)&s.z);
        float2 d = __half22float2(*(const __half2*)&s.w);
        acc[0] += a.x; acc[1] += a.y; acc[2] += b.x; acc[3] += b.y;
        acc[4] += c.x; acc[5] += c.y; acc[6] += d.x; acc[7] += d.y;
    }
    __half2 p0 = __floats2half2_rn(acc[0], acc[1]);
    __half2 p1 = __floats2half2_rn(acc[2], acc[3]);
    __half2 p2 = __floats2half2_rn(acc[4], acc[5]);
    __half2 p3 = __floats2half2_rn(acc[6], acc[7]);
    uint4 pk;
    pk.x = *(uint32_t*)&p0; pk.y = *(uint32_t*)&p1;
    pk.z = *(uint32_t*)&p2; pk.w = *(uint32_t*)&p3;
    ((uint4*)out)[(size_t)w * 32 + lane] = pk;
}

// ---------------- fp16 mma GEMM: 3-stage cp.async pipeline (R11 proven) ----------------
template <int K>
__launch_bounds__(256, 2)
__global__ void k_gemm(const __half* __restrict__ A, const __half* __restrict__ Wt,
                       const float* __restrict__ bias, __half* __restrict__ Hout,
                       float* __restrict__ cs, float* __restrict__ cq, int M)
{
    const int BK = 32, NIT = K / BK, LDA = 40;
    const int STG = 2 * 128 * LDA * 2;
    extern __shared__ char dsm[];
    float* RedS = (float*)dsm;
    float* RedQ = (float*)(dsm + 512);
    uint32_t tbase = (uint32_t)__cvta_generic_to_shared(dsm + 1024);

    int bm = blockIdx.x * 128, bn = blockIdx.y * 128;
    int t = threadIdx.x, lane = t & 31, w = t >> 5;
    int m_warp = (w & 1) * 64;
    int n_warp = (w >> 1) * 32;

    if (t < 128) { RedS[t] = 0.f; RedQ[t] = 0.f; }

    int r0 = t >> 2, s0 = (t & 3) * 8;
    int r1 = r0 + 64;
    int gA0 = bm + r0, gA1 = bm + r1;
    int az0 = (gA0 < M) ? 16 : 0, az1 = (gA1 < M) ? 16 : 0;
    const __half* apB0 = A + (size_t)gA0 * K + s0;
    const __half* apB1 = A + (size_t)gA1 * K + s0;
    const __half* bpB0 = Wt + (size_t)(bn + r0) * K + s0;
    const __half* bpB1 = Wt + (size_t)(bn + r1) * K + s0;
    uint32_t dA0 = (uint32_t)((r0 * LDA + s0) * 2);
    uint32_t dA1 = (uint32_t)((r1 * LDA + s0) * 2);
    uint32_t dB0 = (uint32_t)(128 * LDA * 2) + dA0;
    uint32_t dB1 = (uint32_t)(128 * LDA * 2) + dA1;

    uint32_t offA[4], offB[2];
#pragma unroll
    for (int mt = 0; mt < 4; mt++)
        offA[mt] = (uint32_t)(((m_warp + mt * 16 + (lane & 15)) * LDA + (lane >> 4) * 8) * 2);
#pragma unroll
    for (int p = 0; p < 2; p++)
        offB[p] = (uint32_t)(128 * LDA * 2)
                + (uint32_t)(((n_warp + p * 16 + (lane & 7) + (lane >> 4) * 8) * LDA
                             + ((lane >> 3) & 1) * 8) * 2);

    float acc[4][4][4];
#pragma unroll
    for (int mt = 0; mt < 4; mt++)
#pragma unroll
        for (int nt = 0; nt < 4; nt++)
#pragma unroll
            for (int f = 0; f < 4; f++) acc[mt][nt][f] = 0.f;

#pragma unroll
    for (int pt = 0; pt < 2; pt++) {
        uint32_t sb = tbase + (uint32_t)pt * STG;
        int k0 = pt * BK;
        cp16s(sb + dA0, apB0 + k0, az0);
        cp16s(sb + dA1, apB1 + k0, az1);
        cp16s(sb + dB0, bpB0 + k0, 16);
        cp16s(sb + dB1, bpB1 + k0, 16);
        CP_COMMIT();
    }

#pragma unroll
    for (int it = 0; it < NIT; it++) {
        if (it < NIT - 1) CP_WAIT1(); else CP_WAIT0();
        __syncthreads();
        uint32_t sb = tbase + (uint32_t)(it % 3) * STG;
#pragma unroll
        for (int ks = 0; ks < 2; ks++) {
            uint32_t kb = (uint32_t)(ks * 16 * 2);
            uint32_t af[4][4], bf[4][2];
#pragma unroll
            for (int mt = 0; mt < 4; mt++)
                LDSM_X4(af[mt][0], af[mt][1], af[mt][2], af[mt][3], sb + offA[mt] + kb);
            LDSM_X4(bf[0][0], bf[0][1], bf[1][0], bf[1][1], sb + offB[0] + kb);
            LDSM_X4(bf[2][0], bf[2][1], bf[3][0], bf[3][1], sb + offB[1] + kb);
#pragma unroll
            for (int mt = 0; mt < 4; mt++)
#pragma unroll
                for (int nt = 0; nt < 4; nt++)
                    MMA_F16(acc[mt][nt], af[mt], bf[nt]);
        }
        if (it + 2 < NIT) {
            uint32_t sn = tbase + (uint32_t)((it + 2) % 3) * STG;
            int k0 = (it + 2) * BK;
            cp16s(sn + dA0, apB0 + k0, az0);
            cp16s(sn + dA1, apB1 + k0, az1);
            cp16s(sn + dB0, bpB0 + k0, 16);
            cp16s(sn + dB1, bpB1 + k0, 16);
            CP_COMMIT();
        }
    }
    __syncthreads();

    int ar = lane >> 2;
    int ac2 = (lane & 3) * 2;
#pragma unroll
    for (int nt = 0; nt < 4; nt++) {
        int cc = n_warp + nt * 8 + ac2;
        float b0 = bias[bn + cc], b1 = bias[bn + cc + 1];
        float s0a = 0.f, q0 = 0.f, s1a = 0.f, q1 = 0.f;
#pragma unroll
        for (int mt = 0; mt < 4; mt++) {
            int gr0 = bm + m_warp + mt * 16 + ar;
            int gr1 = gr0 + 8;
            if (gr0 < M) {
                float o0 = acc[mt][nt][0] + b0;
                float o1 = acc[mt][nt][1] + b1;
                *(__half2*)(Hout + (size_t)gr0 * HD + bn + cc) = __floats2half2_rn(o0, o1);
                s0a += o0; q0 += o0 * o0; s1a += o1; q1 += o1 * o1;
            }
            if (gr1 < M) {
                float o2 = acc[mt][nt][2] + b0;
                float o3 = acc[mt][nt][3] + b1;
                *(__half2*)(Hout + (size_t)gr1 * HD + bn + cc) = __floats2half2_rn(o2, o3);
                s0a += o2; q0 += o2 * o2; s1a += o3; q1 += o3 * o3;
            }
        }
        atomicAdd(&RedS[cc], s0a);
        atomicAdd(&RedQ[cc], q0);
        atomicAdd(&RedS[cc + 1], s1a);
        atomicAdd(&RedQ[cc + 1], q1);
    }
    __syncthreads();
    if (t < 128) {
        atomicAdd(&cs[bn + t], RedS[t]);
        atomicAdd(&cq[bn + t], RedQ[t]);
    }
}

// ---------------- fused layer-2 elementwise: xb = relu(bn2(h2)) + relu(bn1(h1)) ----------------
__global__ void k_bnrelu2f(const __half* __restrict__ H1, const __half* __restrict__ H2,
                           const float* __restrict__ g1, const float* __restrict__ b1,
                           const float* __restrict__ g2, const float* __restrict__ b2,
                           __half* __restrict__ out, int M)
{
    __shared__ float sc1[HD], sh1[HD], sc2[HD], sh2[HD];
    int t = threadIdx.x;
    if (blockIdx.x < 64) {
        g_pool[blockIdx.x * 256 + t] = 0.f;
        if (blockIdx.x == 0 && t < NGR) g_cnt[t] = 0.f;
    }
    if (t < HD) {
        float invN = 1.0f / (float)M;
        float m1 = g_cs[t] * invN;
        float v1 = fmaf(-m1, m1, g_cq[t] * invN);
        float s1 = g1[t] * rsqrtf(v1 + 1e-5f);
        sc1[t] = s1; sh1[t] = fmaf(-m1, s1, b1[t]);
        float m2 = g_cs[HD + t] * invN;
        float v2 = fmaf(-m2, m2, g_cq[HD + t] * invN);
        float s2 = g2[t] * rsqrtf(v2 + 1e-5f);
        sc2[t] = s2; sh2[t] = fmaf(-m2, s2, b2[t]);
    }
    __syncthreads();

    int idx = blockIdx.x * blockDim.x + t;
    if (idx >= M * 32) return;
    int c8 = (idx & 31) * 8;
    uint4 u1 = ((const uint4*)H1)[idx];
    uint4 u2 = ((const uint4*)H2)[idx];
    const __half2* p1 = (const __half2*)&u1;
    const __half2* p2 = (const __half2*)&u2;
    float o[8];
#pragma unroll
    for (int q = 0; q < 4; q++) {
        float2 a = __half22float2(p1[q]);
        float2 b = __half22float2(p2[q]);
        int c = c8 + q * 2;
        o[q * 2]     = fmaxf(fmaf(b.x, sc2[c], sh2[c]), 0.f)
                     + fmaxf(fmaf(a.x, sc1[c], sh1[c]), 0.f);
        o[q * 2 + 1] = fmaxf(fmaf(b.y, sc2[c + 1], sh2[c + 1]), 0.f)
                     + fmaxf(fmaf(a.y, sc1[c + 1], sh1[c + 1]), 0.f);
    }
    __half2 q0 = __floats2half2_rn(o[0], o[1]);
    __half2 q1 = __floats2half2_rn(o[2], o[3]);
    __half2 q2 = __floats2half2_rn(o[4], o[5]);
    __half2 q3 = __floats2half2_rn(o[6], o[7]);
    uint4 pk;
    pk.x = *(uint32_t*)&q0; pk.y = *(uint32_t*)&q1;
    pk.z = *(uint32_t*)&q2; pk.w = *(uint32_t*)&q3;
    ((uint4*)out)[idx] = pk;
}

// ---------------- fused pool: x3 = relu(bn3(h3)) + xb computed inline ----------------
__global__ void k_pool3f(const __half* __restrict__ H3, const __half* __restrict__ xb,
                         const float* __restrict__ g3, const float* __restrict__ b3, int N)
{
    __shared__ float sc3[HD], sh3[HD];
    __shared__ int sb[128];
    int t = threadIdx.x;
    if (t < HD) {
        float invN = 1.0f / (float)N;
        float m = g_cs[t] * invN;                      // layer-3 stats (buf0)
        float v = fmaf(-m, m, g_cq[t] * invN);
        float s = g3[t] * rsqrtf(v + 1e-5f);
        sc3[t] = s; sh3[t] = fmaf(-m, s, b3[t]);
    }
    int n0 = blockIdx.x * 128;
    int n1 = n0 + 128; if (n1 > N) n1 = N;
    if (t < n1 - n0) sb[t] = g_batch[n0 + t];
    __syncthreads();
    if (n1 <= n0) return;

    float sc = sc3[t], sh = sh3[t];
    float acc = 0.f;
    int curg = sb[0], cnt = 0;
    for (int n = n0; n < n1; n++) {
        int g = sb[n - n0];
        if (g != curg) {
            atomicAdd(&g_pool[curg * HD + t], acc);
            if (t == 0) atomicAdd(&g_cnt[curg], (float)cnt);
            acc = 0.f; cnt = 0; curg = g;
        }
        float h = __half2float(H3[(size_t)n * HD + t]);
        float r = __half2float(xb[(size_t)n * HD + t]);
        acc += fmaxf(fmaf(h, sc, sh), 0.f) + r;
        cnt++;
    }
    atomicAdd(&g_pool[curg * HD + t], acc);
    if (t == 0) atomicAdd(&g_cnt[curg], (float)cnt);
}

// ---------------- final MLP head (64 graphs) ----------------
__global__ void k_final(const float* __restrict__ fcW1, const float* __restrict__ fcb1,
                        const float* __restrict__ fcW2, const float* __restrict__ fcb2,
                        float* __restrict__ out)
{
    __shared__ float prow[HD];
    __shared__ float hred[HD];
    int g = blockIdx.x, t = threadIdx.x;
    float cnt = fmaxf(g_cnt[g], 1.0f);
    prow[t] = g_pool[g * HD + t] / cnt;
    __syncthreads();
    float acc = fcb1[t];
    for (int k = 0; k < HD; k++)
        acc = fmaf(prow[k], __ldg(fcW1 + (size_t)k * HD + t), acc);
    float h = fmaxf(acc, 0.0f);
    hred[t] = h * fcW2[t];
    __syncthreads();
    for (int s = HD / 2; s > 0; s >>= 1) {
        if (t < s) hred[t] += hred[t + s];
        __syncthreads();
    }
    if (t == 0) out[g] = hred[0] + fcb2[0];
}

// ---------------- launch ----------------
extern "C" void kernel_launch(void* const* d_in, const int* in_sizes, int n_in,
                              void* d_out, int out_size)
{
    int base = 3;
    if (n_in >= 20 && in_sizes[3] == 1) base = 4;

    const float* x   = (const float*)d_in[0];
    const int*   ei  = (const int*)d_in[1];
    const int*   bat = (const int*)d_in[2];
    const float* W1  = (const float*)d_in[base + 0];
    const float* b1  = (const float*)d_in[base + 1];
    const float* W2  = (const float*)d_in[base + 2];
    const float* b2  = (const float*)d_in[base + 3];
    const float* W3  = (const float*)d_in[base + 4];
    const float* b3  = (const float*)d_in[base + 5];
    const float* ga1 = (const float*)d_in[base + 6];
    const float* be1 = (const float*)d_in[base + 7];
    const float* ga2 = (const float*)d_in[base + 8];
    const float* be2 = (const float*)d_in[base + 9];
    const float* ga3 = (const float*)d_in[base + 10];
    const float* be3 = (const float*)d_in[base + 11];
    const float* fcW1 = (const float*)d_in[base + 12];
    const float* fcb1 = (const float*)d_in[base + 13];
    const float* fcW2 = (const float*)d_in[base + 14];
    const float* fcb2 = (const float*)d_in[base + 15];

    int N = in_sizes[0] / 128;
    int E = in_sizes[1] / 2;

    void* p;
    __half *aggh, *xbh, *w1t, *w2t, *w3t, *ha, *hb;
    float *cs, *cq;
    cudaGetSymbolAddress(&p, g_aggh); aggh = (__half*)p;
    cudaGetSymbolAddress(&p, g_hbuf); ha   = (__half*)p; hb = ha + (size_t)NMAX * HD;
    cudaGetSymbolAddress(&p, g_xbh);  xbh  = (__half*)p;
    cudaGetSymbolAddress(&p, g_w1t);  w1t  = (__half*)p;
    cudaGetSymbolAddress(&p, g_w2t);  w2t  = (__half*)p;
    cudaGetSymbolAddress(&p, g_w3t);  w3t  = (__half*)p;
    cudaGetSymbolAddress(&p, g_cs);   cs   = (float*)p;
    cudaGetSymbolAddress(&p, g_cq);   cq   = (float*)p;

    const int SHM = 1024 + 3 * 20480;
    cudaFuncSetAttribute(k_gemm<128>, cudaFuncAttributeMaxDynamicSharedMemorySize, SHM);
    cudaFuncSetAttribute(k_gemm<256>, cudaFuncAttributeMaxDynamicSharedMemorySize, SHM);

    const int tb = 256;
    int ebl = (E + tb - 1) / tb;
    int nb256 = (N + 255) / 256;
    int wbl = (N * 32 + tb - 1) / tb;
    int bnbl = (N * 32 + tb - 1) / tb;
    int nx = (N * 32 + 255) / 256;
    dim3 ggrid((N + 127) / 128, 2);

    // CSR + prep (fused)
    k_convprep<<<ebl + nx + 768, tb>>>(ei, bat, x, W1, W2, W3, E, N, ebl, nx);
    k_bsum<<<nb256, 256>>>(N);
    k_off<<<nb256, 256>>>(N);
    k_fill<<<ebl, tb>>>(E);

    // layer 1: gather (zeros stats0) -> gemm1 -> h_a (stats buf0)
    k_gather128h<<<wbl, tb>>>(aggh, N);
    k_gemm<128><<<ggrid, 256, SHM>>>(aggh, w1t, b1, ha, cs, cq, N);

    // layer 2: fused-BN1 gather on h_a (zeros stats1) -> gemm2 -> h_b (stats buf1)
    k_gather256bn<<<wbl, tb>>>(ha, aggh, ga1, be1, N);
    k_gemm<256><<<ggrid, 256, SHM>>>(aggh, w2t, b2, hb, cs + HD, cq + HD, N);

    // xb = relu(bn2(h_b)) + relu(bn1(h_a))  [also zeroes pool]
    k_bnrelu2f<<<bnbl, tb>>>(ha, hb, ga1, be1, ga2, be2, xbh, N);

    // layer 3: gather on xb (zeros stats0) -> gemm3 -> h_a reused as h3 (stats buf0)
    k_gather256h<<<wbl, tb>>>(xbh, aggh, N);
    k_gemm<256><<<ggrid, 256, SHM>>>(aggh, w3t, b3, ha, cs, cq, N);

    // fused pool: x3 = relu(bn3(h3)) + xb, accumulated per graph on the fly
    k_pool3f<<<(N + 127) / 128, 256>>>(ha, xbh, ga3, be3, N);
    k_final<<<NGR, 256>>>(fcW1, fcb1, fcW2, fcb2, (float*)d_out);
}